// round 5
// baseline (speedup 1.0000x reference)
#include <cuda_runtime.h>
#include <cuda_fp16.h>
#include <math.h>
#include <stdint.h>

// ---------------- problem constants ----------------
#define BATCH 32
#define CCH   768
#define DDIM  64
#define MEMB  512
#define TP    511
#define NVEC  (BATCH * TP)
#define NPART (NVEC / 8)

// ---------------- device scratch (static) ----------------
__device__ __half g_XAh[(size_t)BATCH * 1022 * CCH];
__device__ __half g_XAl[(size_t)BATCH * 1022 * CCH];
__device__ __half g_XBh[(size_t)BATCH * 1022 * CCH];
__device__ __half g_XBl[(size_t)BATCH * 1022 * CCH];
__device__ __half g_M1h[(size_t)BATCH * 1024 * 128];
__device__ __half g_M1l[(size_t)BATCH * 1024 * 128];
__device__ __half g_W1h[768 * 3 * 128], g_W1l[768 * 3 * 128];
__device__ __half g_W2h[768 * 3 * 768], g_W2l[768 * 3 * 768];
__device__ __half g_W3h[768 * 4 * 768], g_W3l[768 * 4 * 768];
__device__ __half g_W4h[768 * 3 * 768], g_W4l[768 * 3 * 768];
__device__ __half g_W5h[768 * 3 * 768], g_W5l[768 * 3 * 768];
__device__ float g_C5[(size_t)BATCH * TP * CCH];     // [b][t][c] fp32
__device__ float g_z[(size_t)NVEC * DDIM];
__device__ float g_Et[DDIM * MEMB];
__device__ float g_esq[MEMB];
__device__ int   g_counts[MEMB];
__device__ float g_partial[NPART];

// ---------------- helpers ----------------
__device__ __forceinline__ uint32_t smem_u32(const void* p) {
    uint32_t a;
    asm("{ .reg .u64 t; cvta.to.shared.u64 t, %1; cvt.u32.u64 %0, t; }"
        : "=r"(a) : "l"(p));
    return a;
}

#define LDMX4(r0, r1, r2, r3, addr) \
    asm volatile("ldmatrix.sync.aligned.m8n8.x4.shared.b16 {%0,%1,%2,%3}, [%4];" \
        : "=r"(r0), "=r"(r1), "=r"(r2), "=r"(r3) : "r"(addr))

__device__ __forceinline__ void mma16816(float* d, const uint32_t* a, const uint32_t* b) {
    asm volatile(
        "mma.sync.aligned.m16n8k16.row.col.f32.f16.f16.f32 "
        "{%0,%1,%2,%3}, {%4,%5,%6,%7}, {%8,%9}, {%0,%1,%2,%3};"
        : "+f"(d[0]), "+f"(d[1]), "+f"(d[2]), "+f"(d[3])
        : "r"(a[0]), "r"(a[1]), "r"(a[2]), "r"(a[3]), "r"(b[0]), "r"(b[1]));
}

__device__ __forceinline__ void cp16(uint32_t dst, const void* src, bool pred) {
    asm volatile("cp.async.cg.shared.global [%0], [%1], 16, %2;"
        :: "r"(dst), "l"(src), "r"(pred ? 16 : 0));
}
#define CP_COMMIT() asm volatile("cp.async.commit_group;" ::: "memory")
#define CP_WAIT1()  asm volatile("cp.async.wait_group 1;" ::: "memory")
#define CP_WAIT0()  asm volatile("cp.async.wait_group 0;" ::: "memory")

// smem: double buffer, each buf = A(20480) + B(20480). total 81920.
#define ABUF   20480
#define BUFSZ  40960
#define SM_TOT 81920
#define RSTR   80        // bytes per 32-half row (64B data + 16B pad)

// ============================================================
// Implicit-GEMM conv1d + BN + ReLU via mma.sync fp16 3-term split.
// BM=128 (co) x BN=128 (t), BK=32. 256 thr (2 CTAs/SM), warp tile 64x32.
// cp.async double-buffered loads, per-plane A frag staging (<=128 regs).
// ============================================================
template<int KTAP, int S, int P, bool SPLITOUT>
__global__ void __launch_bounds__(256, 2) conv_mma(
    const __half* __restrict__ Xh, const __half* __restrict__ Xl,
    const __half* __restrict__ Wh, const __half* __restrict__ Wl,
    const float* __restrict__ gam, const float* __restrict__ bet,
    const float* __restrict__ mu,  const float* __restrict__ var,
    __half* __restrict__ Yh, __half* __restrict__ Yl, float* __restrict__ Yf,
    int Cin, int Tin, int Tout)
{
    extern __shared__ char smem[];
    const uint32_t sb = smem_u32(smem);
    const int tid = threadIdx.x;
    const int lane = tid & 31, w = tid >> 5;
    const int mw = w & 1, nw = w >> 1;          // warp grid: 2(m) x 4(n)
    const int b = blockIdx.z, m0 = blockIdx.y * 128, t0 = blockIdx.x * 128;
    const int Kp = KTAP * Cin;
    const int cich = Cin >> 5;
    const int nchunk = Kp >> 5;

    float acc[4][4][4];
    #pragma unroll
    for (int i = 0; i < 4; i++)
        #pragma unroll
        for (int j = 0; j < 4; j++)
            #pragma unroll
            for (int r = 0; r < 4; r++) acc[i][j][r] = 0.f;

    // per-thread load decode: idx = i*256+tid -> plane=idx>>9, row=(idx>>2)&127, seg=idx&3
    const int l_pl  = (tid * 4) >> 9;          // constant per thread across i? no — recompute in loop
    (void)l_pl;

    auto issue = [&](int kc, int buf) {
        const int tap = kc / cich;
        const int ci0 = (kc - tap * cich) << 5;
        const uint32_t base = sb + buf * BUFSZ;
        #pragma unroll
        for (int i = 0; i < 4; i++) {
            const int idx = i * 256 + tid;
            const int pl = idx >> 9, r = (idx >> 2) & 127, seg = idx & 3;
            const __half* W = pl ? Wl : Wh;
            cp16(base + pl * 10240 + r * RSTR + seg * 16,
                 W + (size_t)(m0 + r) * Kp + kc * 32 + seg * 8, true);
            const int t_in = (t0 + r) * S + tap - P;
            const bool ok = (t_in >= 0) && (t_in < Tin);
            const int tc = t_in < 0 ? 0 : (t_in >= Tin ? Tin - 1 : t_in);
            const __half* X = pl ? Xl : Xh;
            cp16(base + ABUF + pl * 10240 + r * RSTR + seg * 16,
                 X + ((size_t)b * Tin + tc) * Cin + ci0 + seg * 8, ok);
        }
    };

    // per-thread ldmatrix base offsets (within one plane)
    const uint32_t aoff = (uint32_t)((mw * 64 + (lane & 15)) * RSTR + (lane >> 4) * 16);
    const uint32_t boff = (uint32_t)((nw * 32 + (lane & 7) + ((lane >> 4) << 3)) * RSTR
                                     + ((lane >> 3) & 1) * 16);

    issue(0, 0);
    CP_COMMIT();

    for (int kc = 0; kc < nchunk; kc++) {
        const int cur = kc & 1;
        if (kc + 1 < nchunk) {
            issue(kc + 1, cur ^ 1);
            CP_COMMIT();
            CP_WAIT1();
        } else {
            CP_WAIT0();
        }
        __syncthreads();

        const uint32_t sa  = sb + cur * BUFSZ;
        const uint32_t sbB = sa + ABUF;
        #pragma unroll
        for (int ks = 0; ks < 2; ks++) {
            uint32_t bf0[4][2], bf1[4][2], af[4][4];
            const uint32_t pb = sbB + boff + ks * 32;
            #pragma unroll
            for (int nc = 0; nc < 2; nc++) {
                LDMX4(bf0[2*nc][0], bf0[2*nc][1], bf0[2*nc+1][0], bf0[2*nc+1][1],
                      pb + nc * (16 * RSTR));
                LDMX4(bf1[2*nc][0], bf1[2*nc][1], bf1[2*nc+1][0], bf1[2*nc+1][1],
                      pb + 10240 + nc * (16 * RSTR));
            }
            const uint32_t pa = sa + aoff + ks * 32;
            #pragma unroll
            for (int mt = 0; mt < 4; mt++)
                LDMX4(af[mt][0], af[mt][1], af[mt][2], af[mt][3],
                      pa + mt * (16 * RSTR));
            #pragma unroll
            for (int mt = 0; mt < 4; mt++)
                #pragma unroll
                for (int nt = 0; nt < 4; nt++) {
                    mma16816(acc[mt][nt], af[mt], bf0[nt]);   // hi*hi
                    mma16816(acc[mt][nt], af[mt], bf1[nt]);   // hi*lo
                }
            #pragma unroll
            for (int mt = 0; mt < 4; mt++)
                LDMX4(af[mt][0], af[mt][1], af[mt][2], af[mt][3],
                      pa + 10240 + mt * (16 * RSTR));
            #pragma unroll
            for (int mt = 0; mt < 4; mt++)
                #pragma unroll
                for (int nt = 0; nt < 4; nt++)
                    mma16816(acc[mt][nt], af[mt], bf0[nt]);   // lo*hi
        }
        __syncthreads();
    }

    // ---------- epilogue: stage [n][m] in smem, BN+ReLU, coalesced stores ----------
    float* eps = (float*)(smem + w * 9216);   // 32 rows x 72 floats
    #pragma unroll
    for (int mt = 0; mt < 4; mt++)
        #pragma unroll
        for (int nt = 0; nt < 4; nt++)
            #pragma unroll
            for (int r = 0; r < 4; r++) {
                const int nl = nt * 8 + 2 * (lane & 3) + (r & 1);
                const int ml = mt * 16 + (lane >> 2) + ((r >> 1) << 3);
                eps[nl * 72 + ml] = acc[mt][nt][r];
            }
    __syncwarp();

    const int cg = m0 + mw * 64 + lane * 2;
    const float inv0 = gam[cg] * rsqrtf(var[cg] + 1e-5f);
    const float sh0  = bet[cg] - mu[cg] * inv0;
    const float inv1 = gam[cg + 1] * rsqrtf(var[cg + 1] + 1e-5f);
    const float sh1  = bet[cg + 1] - mu[cg + 1] * inv1;

    #pragma unroll 4
    for (int rn = 0; rn < 32; rn++) {
        const int t = t0 + nw * 32 + rn;
        if (t < Tout) {
            float v0 = fmaf(eps[rn * 72 + lane * 2], inv0, sh0);
            float v1 = fmaf(eps[rn * 72 + lane * 2 + 1], inv1, sh1);
            v0 = v0 > 0.f ? v0 : 0.f;
            v1 = v1 > 0.f ? v1 : 0.f;
            const size_t o = ((size_t)b * Tout + t) * CCH + cg;
            if (SPLITOUT) {
                const __half h0 = __float2half_rn(v0);
                const __half h1 = __float2half_rn(v1);
                const __half l0 = __float2half_rn(v0 - __half2float(h0));
                const __half l1 = __float2half_rn(v1 - __half2float(h1));
                *(__half2*)(Yh + o) = __halves2half2(h0, h1);
                *(__half2*)(Yl + o) = __halves2half2(l0, l1);
            } else {
                *(float2*)(Yf + o) = make_float2(v0, v1);
            }
        }
    }
}

// ============================================================
// Fused weight prep: all 5 layers in ONE launch (keeps ncu -s 5 on conv4).
// Reorder [co][ci][k] -> [co][tap*Cpad+ci], split hi/lo fp16.
// ============================================================
__device__ __forceinline__ void w_split(const float* __restrict__ src,
                                        __half* dh, __half* dl,
                                        int Cin, int Cpad, int K, int idx)
{
    const int ci = idx % Cpad;
    const int r  = idx / Cpad;
    const int k  = r % K, co = r / K;
    const float v = (ci < Cin) ? src[((size_t)co * Cin + ci) * K + k] : 0.f;
    const __half h = __float2half_rn(v);
    dh[idx] = h;
    dl[idx] = __float2half_rn(v - __half2float(h));
}

#define NW1 (768*3*128)
#define NW2 (768*3*768)
#define NW3 (768*4*768)

__global__ void prep_w_all(const float* __restrict__ w1, const float* __restrict__ w2,
                           const float* __restrict__ w3, const float* __restrict__ w4,
                           const float* __restrict__ w5)
{
    int idx = blockIdx.x * 256 + threadIdx.x;
    if (idx < NW1) { w_split(w1, g_W1h, g_W1l, 80, 128, 3, idx); return; }
    idx -= NW1;
    if (idx < NW2) { w_split(w2, g_W2h, g_W2l, 768, 768, 3, idx); return; }
    idx -= NW2;
    if (idx < NW3) { w_split(w3, g_W3h, g_W3l, 768, 768, 4, idx); return; }
    idx -= NW3;
    if (idx < NW2) { w_split(w4, g_W4h, g_W4l, 768, 768, 3, idx); return; }
    idx -= NW2;
    if (idx < NW2) { w_split(w5, g_W5h, g_W5l, 768, 768, 3, idx); return; }
}
#define NWTOT (NW1 + 3*NW2 + NW3)

// ============================================================
// Prep: transpose mels [b][80][1024] -> [b][1024][128] halves hi/lo (pad ch).
// ============================================================
__global__ void prep_mels(const float* __restrict__ mels)
{
    __shared__ float ts[80][33];
    const int b = blockIdx.y, t0 = blockIdx.x * 32, tid = threadIdx.x;
    const int tl = tid & 31, cw = tid >> 5;
    for (int c = cw; c < 80; c += 8)
        ts[c][tl] = mels[((size_t)b * 80 + c) * 1024 + t0 + tl];
    __syncthreads();
    const int c0 = (tid & 31) * 4, tw = tid >> 5;
    for (int tt = tw; tt < 32; tt += 8) {
        #pragma unroll
        for (int j = 0; j < 4; j++) {
            const int c = c0 + j;
            const float x = (c < 80) ? ts[c][tt] : 0.f;
            const __half h = __float2half_rn(x);
            const size_t o = ((size_t)b * 1024 + t0 + tt) * 128 + c;
            g_M1h[o] = h;
            g_M1l[o] = __float2half_rn(x - __half2float(h));
        }
    }
}

// ============================================================
// conv6 (1x1, 768->64) + bias + transpose. X is [b][t][768] fp32.
// ============================================================
__global__ __launch_bounds__(256) void conv6_kernel(
    const float* __restrict__ X, const float* __restrict__ W6,
    const float* __restrict__ b6, float* __restrict__ Z)
{
    __shared__ float Xs[64][65];
    __shared__ float Ws[64][65];
    const int tid = threadIdx.x;
    const int b   = blockIdx.y;
    const int t0  = blockIdx.x * 64;
    const int tdx = tid & 15;
    const int ttx = tid >> 4;

    float acc[4][4];
    #pragma unroll
    for (int i = 0; i < 4; i++)
        #pragma unroll
        for (int j = 0; j < 4; j++) acc[i][j] = 0.f;

    const int lt = tid & 63;
    const int lr = tid >> 6;

    for (int c0 = 0; c0 < CCH; c0 += 64) {
        #pragma unroll
        for (int r = 0; r < 16; r++) {
            const int trow = t0 + lr + 4 * r;
            Xs[lt][lr + 4 * r] = (trow < TP)
                ? X[((size_t)b * TP + trow) * CCH + c0 + lt] : 0.f;
            const int d = lr + r * 4;
            Ws[d][lt] = W6[(size_t)d * CCH + c0 + lt];
        }
        __syncthreads();
        #pragma unroll 8
        for (int ci = 0; ci < 64; ci++) {
            float wv[4], x[4];
            #pragma unroll
            for (int i = 0; i < 4; i++) wv[i] = Ws[tdx * 4 + i][ci];
            #pragma unroll
            for (int j = 0; j < 4; j++) x[j] = Xs[ci][ttx * 4 + j];
            #pragma unroll
            for (int i = 0; i < 4; i++)
                #pragma unroll
                for (int j = 0; j < 4; j++)
                    acc[i][j] = fmaf(wv[i], x[j], acc[i][j]);
        }
        __syncthreads();
    }
    #pragma unroll
    for (int i = 0; i < 4; i++) {
        const int d = tdx * 4 + i;
        const float bias = b6[d];
        #pragma unroll
        for (int j = 0; j < 4; j++) {
            const int t = t0 + ttx * 4 + j;
            if (t < TP)
                Z[((size_t)(b * TP + t)) * DDIM + d] = acc[i][j] + bias;
        }
    }
}

// ============================================================
// VQ prep / VQ / finalize (unchanged, validated)
// ============================================================
__global__ void prep_vq(const float* __restrict__ E)
{
    const int e = threadIdx.x;
    float s = 0.f;
    #pragma unroll
    for (int d = 0; d < DDIM; d++) {
        const float v = E[(size_t)e * DDIM + d];
        s = fmaf(v, v, s);
        g_Et[d * MEMB + e] = v;
    }
    g_esq[e] = s;
    g_counts[e] = 0;
}

__global__ __launch_bounds__(256) void vq_kernel(
    const float* __restrict__ Z, const float* __restrict__ E,
    float* __restrict__ out)
{
    __shared__ float zsh[8][64];
    __shared__ float pw[8];
    const int tid  = threadIdx.x;
    const int w    = tid >> 5;
    const int lane = tid & 31;
    const int vec  = blockIdx.x * 8 + w;

    zsh[w][lane]      = Z[(size_t)vec * 64 + lane];
    zsh[w][lane + 32] = Z[(size_t)vec * 64 + lane + 32];
    __syncwarp();

    float best = 3.4e38f;
    int   bidx = 0;
    #pragma unroll
    for (int i = 0; i < 16; i++) {
        const int e = lane + 32 * i;
        float dot = 0.f;
        #pragma unroll
        for (int d = 0; d < 64; d++)
            dot = fmaf(zsh[w][d], g_Et[d * MEMB + e], dot);
        const float dist = g_esq[e] - 2.f * dot;
        if (dist < best) { best = dist; bidx = e; }
    }
    #pragma unroll
    for (int off = 16; off > 0; off >>= 1) {
        const float ob = __shfl_down_sync(0xFFFFFFFFu, best, off);
        const int   oi = __shfl_down_sync(0xFFFFFFFFu, bidx, off);
        if (ob < best || (ob == best && oi < bidx)) { best = ob; bidx = oi; }
    }
    bidx = __shfl_sync(0xFFFFFFFFu, bidx, 0);

    float lsum = 0.f;
    #pragma unroll
    for (int h = 0; h < 2; h++) {
        const int d   = lane + 32 * h;
        const float zv = zsh[w][d];
        const float q  = E[(size_t)bidx * 64 + d];
        out[(size_t)vec * 64 + d] = zv + (q - zv);
        const float diff = zv - q;
        lsum = fmaf(diff, diff, lsum);
    }
    #pragma unroll
    for (int off = 16; off > 0; off >>= 1)
        lsum += __shfl_down_sync(0xFFFFFFFFu, lsum, off);

    if (lane == 0) {
        pw[w] = lsum;
        atomicAdd(&g_counts[bidx], 1);
    }
    __syncthreads();
    if (tid == 0) {
        float s = 0.f;
        #pragma unroll
        for (int i = 0; i < 8; i++) s += pw[i];
        g_partial[blockIdx.x] = s;
    }
}

__global__ __launch_bounds__(1024) void finalize_kernel(float* __restrict__ out)
{
    __shared__ float sh[1024];
    const int tid = threadIdx.x;
    float s = 0.f;
    for (int i = tid; i < NPART; i += 1024) s += g_partial[i];
    sh[tid] = s; __syncthreads();
    for (int off = 512; off > 0; off >>= 1) {
        if (tid < off) sh[tid] += sh[tid + off];
        __syncthreads();
    }
    const float total = sh[0];
    __syncthreads();
    float h = 0.f;
    if (tid < MEMB) {
        const float p = (float)g_counts[tid] / (float)NVEC;
        h = p * logf(p + 1e-10f);
    }
    sh[tid] = h; __syncthreads();
    for (int off = 512; off > 0; off >>= 1) {
        if (tid < off) sh[tid] += sh[tid + off];
        __syncthreads();
    }
    if (tid == 0) {
        out[(size_t)NVEC * DDIM]     = 0.25f * total / (float)((size_t)NVEC * DDIM);
        out[(size_t)NVEC * DDIM + 1] = expf(-sh[0]);
    }
}

// ============================================================
// launch
// ============================================================
extern "C" void kernel_launch(void* const* d_in, const int* in_sizes, int n_in,
                              void* d_out, int out_size)
{
    const float* mels  = (const float*)d_in[0];
    const float* w1    = (const float*)d_in[1];
    const float* w2    = (const float*)d_in[2];
    const float* w3    = (const float*)d_in[3];
    const float* w4    = (const float*)d_in[4];
    const float* w5    = (const float*)d_in[5];
    const float* w6    = (const float*)d_in[6];
    const float* b6    = (const float*)d_in[7];
    const float* gamma = (const float*)d_in[8];
    const float* beta  = (const float*)d_in[9];
    const float* mean  = (const float*)d_in[10];
    const float* var   = (const float*)d_in[11];
    const float* emb   = (const float*)d_in[12];
    float* out = (float*)d_out;

    __half *XAh, *XAl, *XBh, *XBl, *M1h, *M1l;
    __half *W1h, *W1l, *W2h, *W2l, *W3h, *W3l, *W4h, *W4l, *W5h, *W5l;
    float *C5, *zbuf;
    cudaGetSymbolAddress((void**)&XAh, g_XAh);
    cudaGetSymbolAddress((void**)&XAl, g_XAl);
    cudaGetSymbolAddress((void**)&XBh, g_XBh);
    cudaGetSymbolAddress((void**)&XBl, g_XBl);
    cudaGetSymbolAddress((void**)&M1h, g_M1h);
    cudaGetSymbolAddress((void**)&M1l, g_M1l);
    cudaGetSymbolAddress((void**)&C5,  g_C5);
    cudaGetSymbolAddress((void**)&zbuf, g_z);
    cudaGetSymbolAddress((void**)&W1h, g_W1h); cudaGetSymbolAddress((void**)&W1l, g_W1l);
    cudaGetSymbolAddress((void**)&W2h, g_W2h); cudaGetSymbolAddress((void**)&W2l, g_W2l);
    cudaGetSymbolAddress((void**)&W3h, g_W3h); cudaGetSymbolAddress((void**)&W3l, g_W3l);
    cudaGetSymbolAddress((void**)&W4h, g_W4h); cudaGetSymbolAddress((void**)&W4l, g_W4l);
    cudaGetSymbolAddress((void**)&W5h, g_W5h); cudaGetSymbolAddress((void**)&W5l, g_W5l);

    cudaFuncSetAttribute(conv_mma<3,1,0,true>,  cudaFuncAttributeMaxDynamicSharedMemorySize, SM_TOT);
    cudaFuncSetAttribute(conv_mma<3,1,1,true>,  cudaFuncAttributeMaxDynamicSharedMemorySize, SM_TOT);
    cudaFuncSetAttribute(conv_mma<4,2,1,true>,  cudaFuncAttributeMaxDynamicSharedMemorySize, SM_TOT);
    cudaFuncSetAttribute(conv_mma<3,1,1,false>, cudaFuncAttributeMaxDynamicSharedMemorySize, SM_TOT);

    // --- prep (2 launches so ncu -s 5 profiles conv4) ---
    prep_w_all<<<(NWTOT + 255)/256, 256>>>(w1, w2, w3, w4, w5);
    prep_mels<<<dim3(32, BATCH), 256>>>(mels);

    // --- conv stack (mma.sync fp16 3-term split) ---
    conv_mma<3,1,0,true><<<dim3(8, 6, BATCH), 256, SM_TOT>>>(
        M1h, M1l, W1h, W1l, gamma, beta, mean, var,
        XAh, XAl, nullptr, 128, 1024, 1022);
    conv_mma<3,1,1,true><<<dim3(8, 6, BATCH), 256, SM_TOT>>>(
        XAh, XAl, W2h, W2l, gamma+CCH, beta+CCH, mean+CCH, var+CCH,
        XBh, XBl, nullptr, 768, 1022, 1022);
    conv_mma<4,2,1,true><<<dim3(4, 6, BATCH), 256, SM_TOT>>>(
        XBh, XBl, W3h, W3l, gamma+2*CCH, beta+2*CCH, mean+2*CCH, var+2*CCH,
        XAh, XAl, nullptr, 768, 1022, 511);
    conv_mma<3,1,1,true><<<dim3(4, 6, BATCH), 256, SM_TOT>>>(
        XAh, XAl, W4h, W4l, gamma+3*CCH, beta+3*CCH, mean+3*CCH, var+3*CCH,
        XBh, XBl, nullptr, 768, 511, 511);
    conv_mma<3,1,1,false><<<dim3(4, 6, BATCH), 256, SM_TOT>>>(
        XBh, XBl, W5h, W5l, gamma+4*CCH, beta+4*CCH, mean+4*CCH, var+4*CCH,
        nullptr, nullptr, C5, 768, 511, 511);

    // --- tail ---
    conv6_kernel<<<dim3(8, BATCH), 256>>>(C5, w6, b6, zbuf);
    prep_vq<<<1, MEMB>>>(emb);
    vq_kernel<<<NPART, 256>>>(zbuf, emb, out);
    finalize_kernel<<<1, 1024>>>(out);
}

// round 6
// speedup vs baseline: 1.3571x; 1.3571x over previous
#include <cuda_runtime.h>
#include <cuda_fp16.h>
#include <math.h>
#include <stdint.h>

// ---------------- problem constants ----------------
#define BATCH 32
#define CCH   768
#define DDIM  64
#define MEMB  512
#define TP    511
#define NVEC  (BATCH * TP)
#define NPART (NVEC / 8)

// ---------------- device scratch (static) ----------------
__device__ __half g_XAh[(size_t)BATCH * 1022 * CCH];
__device__ __half g_XAl[(size_t)BATCH * 1022 * CCH];
__device__ __half g_XBh[(size_t)BATCH * 1022 * CCH];
__device__ __half g_XBl[(size_t)BATCH * 1022 * CCH];
__device__ __half g_M1h[(size_t)BATCH * 1024 * 128];
__device__ __half g_M1l[(size_t)BATCH * 1024 * 128];
__device__ __half g_W1h[768 * 3 * 128], g_W1l[768 * 3 * 128];
__device__ __half g_W2h[768 * 3 * 768], g_W2l[768 * 3 * 768];
__device__ __half g_W3h[768 * 4 * 768], g_W3l[768 * 4 * 768];
__device__ __half g_W4h[768 * 3 * 768], g_W4l[768 * 3 * 768];
__device__ __half g_W5h[768 * 3 * 768], g_W5l[768 * 3 * 768];
__device__ float g_C5[(size_t)BATCH * TP * CCH];     // [b][t][c] fp32
__device__ float g_z[(size_t)NVEC * DDIM];
__device__ float g_Et[DDIM * MEMB];
__device__ float g_esq[MEMB];
__device__ int   g_counts[MEMB];
__device__ float g_partial[NPART];

// ---------------- helpers ----------------
__device__ __forceinline__ uint32_t smem_u32(const void* p) {
    uint32_t a;
    asm("{ .reg .u64 t; cvta.to.shared.u64 t, %1; cvt.u32.u64 %0, t; }"
        : "=r"(a) : "l"(p));
    return a;
}

#define LDMX4(r0, r1, r2, r3, addr) \
    asm volatile("ldmatrix.sync.aligned.m8n8.x4.shared.b16 {%0,%1,%2,%3}, [%4];" \
        : "=r"(r0), "=r"(r1), "=r"(r2), "=r"(r3) : "r"(addr))

__device__ __forceinline__ void mma16816(float* d, const uint32_t* a, const uint32_t* b) {
    asm volatile(
        "mma.sync.aligned.m16n8k16.row.col.f32.f16.f16.f32 "
        "{%0,%1,%2,%3}, {%4,%5,%6,%7}, {%8,%9}, {%0,%1,%2,%3};"
        : "+f"(d[0]), "+f"(d[1]), "+f"(d[2]), "+f"(d[3])
        : "r"(a[0]), "r"(a[1]), "r"(a[2]), "r"(a[3]), "r"(b[0]), "r"(b[1]));
}

__device__ __forceinline__ void cp16(uint32_t dst, const void* src, bool pred) {
    asm volatile("cp.async.cg.shared.global [%0], [%1], 16, %2;"
        :: "r"(dst), "l"(src), "r"(pred ? 16 : 0));
}
#define CP_COMMIT() asm volatile("cp.async.commit_group;" ::: "memory")
#define CP_WAIT0()  asm volatile("cp.async.wait_group 0;" ::: "memory")

// smem: 2 buffers, each = A(40960) + B(40960). total 163840.
// Each tile = 4 (plane,sub) sheets of 128 rows x 80B (32 halves + 16B pad).
#define RSTR   80
#define PLN    10240
#define ABUF   40960
#define BUFSZ  81920
#define SM_TOT 163840

// ============================================================
// Implicit-GEMM conv1d + BN + ReLU via mma.sync fp16 3-term split.
// BM=128 (co) x BN=128 (t), BK=64. 256 thr, warp tile 64x32.
// 2-stage cp.async pipeline, ONE __syncthreads per chunk.
// ============================================================
template<int KTAP, int S, int P, int CIN, bool SPLITOUT>
__global__ void __launch_bounds__(256) conv_mma(
    const __half* __restrict__ Xh, const __half* __restrict__ Xl,
    const __half* __restrict__ Wh, const __half* __restrict__ Wl,
    const float* __restrict__ gam, const float* __restrict__ bet,
    const float* __restrict__ mu,  const float* __restrict__ var,
    __half* __restrict__ Yh, __half* __restrict__ Yl, float* __restrict__ Yf,
    int Tin, int Tout)
{
    extern __shared__ char smem[];
    const uint32_t sb = smem_u32(smem);
    const int tid = threadIdx.x;
    const int lane = tid & 31, w = tid >> 5;
    const int mw = w & 1, nw = w >> 1;          // warp grid: 2(m) x 4(n)
    const int b = blockIdx.z, m0 = blockIdx.y * 128, t0 = blockIdx.x * 128;
    constexpr int Kp = KTAP * CIN;
    constexpr int nchunk = Kp / 64;

    float acc[4][4][4];
    #pragma unroll
    for (int i = 0; i < 4; i++)
        #pragma unroll
        for (int j = 0; j < 4; j++)
            #pragma unroll
            for (int r = 0; r < 4; r++) acc[i][j][r] = 0.f;

    // cp.async loader: 16 x 16B per thread (A: 8, B: 8)
    auto issue = [&](int kc, int buf) {
        const int tap = (kc * 64) / CIN;
        const int ci0 = (kc * 64) % CIN;
        const uint32_t base = sb + buf * BUFSZ;
        #pragma unroll
        for (int i = 0; i < 8; i++) {
            const int idx = i * 256 + tid;          // 0..2047
            const int ps = idx >> 9;                // (plane*2 + sub): 0..3
            const int r = (idx >> 2) & 127, seg = idx & 3;
            const int pl = ps >> 1, sub = ps & 1;
            const __half* W = pl ? Wl : Wh;
            cp16(base + ps * PLN + r * RSTR + seg * 16,
                 W + (size_t)(m0 + r) * Kp + kc * 64 + sub * 32 + seg * 8, true);
            const int t_in = (t0 + r) * S + tap - P;
            const bool ok = (t_in >= 0) && (t_in < Tin);
            const int tc = ok ? t_in : 0;
            const __half* X = pl ? Xl : Xh;
            cp16(base + ABUF + ps * PLN + r * RSTR + seg * 16,
                 X + ((size_t)b * Tin + tc) * CIN + ci0 + sub * 32 + seg * 8, ok);
        }
    };

    // per-thread ldmatrix base offsets (within one (plane,sub) sheet)
    const uint32_t aoff = (uint32_t)((mw * 64 + (lane & 15)) * RSTR + (lane >> 4) * 16);
    const uint32_t boff = (uint32_t)((nw * 32 + (lane & 7) + ((lane >> 4) << 3)) * RSTR
                                     + ((lane >> 3) & 1) * 16);

    issue(0, 0);
    CP_COMMIT();

    for (int kc = 0; kc < nchunk; kc++) {
        CP_WAIT0();
        __syncthreads();        // buf[kc] visible; all warps done reading buf[kc-1]
        if (kc + 1 < nchunk) {
            issue(kc + 1, (kc + 1) & 1);    // overlaps with compute below
            CP_COMMIT();
        }
        const uint32_t sa  = sb + (kc & 1) * BUFSZ;
        const uint32_t sbB = sa + ABUF;
        #pragma unroll
        for (int ks = 0; ks < 4; ks++) {
            const int sub = ks >> 1, inn = (ks & 1) * 32;
            uint32_t af[2][4][4], bf[2][4][2];
            const uint32_t pb = sbB + sub * PLN + boff + inn;
            #pragma unroll
            for (int nc = 0; nc < 2; nc++) {
                LDMX4(bf[0][2*nc][0], bf[0][2*nc][1], bf[0][2*nc+1][0], bf[0][2*nc+1][1],
                      pb + nc * (16 * RSTR));
                LDMX4(bf[1][2*nc][0], bf[1][2*nc][1], bf[1][2*nc+1][0], bf[1][2*nc+1][1],
                      pb + 2 * PLN + nc * (16 * RSTR));
            }
            const uint32_t pa = sa + sub * PLN + aoff + inn;
            #pragma unroll
            for (int mt = 0; mt < 4; mt++)
                LDMX4(af[0][mt][0], af[0][mt][1], af[0][mt][2], af[0][mt][3],
                      pa + mt * (16 * RSTR));
            #pragma unroll
            for (int mt = 0; mt < 4; mt++)
                LDMX4(af[1][mt][0], af[1][mt][1], af[1][mt][2], af[1][mt][3],
                      pa + 2 * PLN + mt * (16 * RSTR));
            // 3-phase ordering: maximal independent MMA chains
            #pragma unroll
            for (int mt = 0; mt < 4; mt++)
                #pragma unroll
                for (int nt = 0; nt < 4; nt++)
                    mma16816(acc[mt][nt], af[0][mt], bf[0][nt]);   // hi*hi
            #pragma unroll
            for (int mt = 0; mt < 4; mt++)
                #pragma unroll
                for (int nt = 0; nt < 4; nt++)
                    mma16816(acc[mt][nt], af[0][mt], bf[1][nt]);   // hi*lo
            #pragma unroll
            for (int mt = 0; mt < 4; mt++)
                #pragma unroll
                for (int nt = 0; nt < 4; nt++)
                    mma16816(acc[mt][nt], af[1][mt], bf[0][nt]);   // lo*hi
        }
    }
    __syncthreads();   // protect smem reuse by epilogue

    // ---------- epilogue: stage [n][m] in smem, BN+ReLU, coalesced stores ----------
    float* eps = (float*)(smem + w * 9216);   // 32 rows x 72 floats
    #pragma unroll
    for (int mt = 0; mt < 4; mt++)
        #pragma unroll
        for (int nt = 0; nt < 4; nt++)
            #pragma unroll
            for (int r = 0; r < 4; r++) {
                const int nl = nt * 8 + 2 * (lane & 3) + (r & 1);
                const int ml = mt * 16 + (lane >> 2) + ((r >> 1) << 3);
                eps[nl * 72 + ml] = acc[mt][nt][r];
            }
    __syncwarp();

    const int cg = m0 + mw * 64 + lane * 2;
    const float inv0 = gam[cg] * rsqrtf(var[cg] + 1e-5f);
    const float sh0  = bet[cg] - mu[cg] * inv0;
    const float inv1 = gam[cg + 1] * rsqrtf(var[cg + 1] + 1e-5f);
    const float sh1  = bet[cg + 1] - mu[cg + 1] * inv1;

    #pragma unroll 4
    for (int rn = 0; rn < 32; rn++) {
        const int t = t0 + nw * 32 + rn;
        if (t < Tout) {
            float v0 = fmaf(eps[rn * 72 + lane * 2], inv0, sh0);
            float v1 = fmaf(eps[rn * 72 + lane * 2 + 1], inv1, sh1);
            v0 = v0 > 0.f ? v0 : 0.f;
            v1 = v1 > 0.f ? v1 : 0.f;
            const size_t o = ((size_t)b * Tout + t) * CCH + cg;
            if (SPLITOUT) {
                const __half h0 = __float2half_rn(v0);
                const __half h1 = __float2half_rn(v1);
                const __half l0 = __float2half_rn(v0 - __half2float(h0));
                const __half l1 = __float2half_rn(v1 - __half2float(h1));
                *(__half2*)(Yh + o) = __halves2half2(h0, h1);
                *(__half2*)(Yl + o) = __halves2half2(l0, l1);
            } else {
                *(float2*)(Yf + o) = make_float2(v0, v1);
            }
        }
    }
}

// ============================================================
// Fused weight prep (one launch): [co][ci][k] -> [co][tap*Cpad+ci], hi/lo fp16.
// ============================================================
__device__ __forceinline__ void w_split(const float* __restrict__ src,
                                        __half* dh, __half* dl,
                                        int Cin, int Cpad, int K, int idx)
{
    const int ci = idx % Cpad;
    const int r  = idx / Cpad;
    const int k  = r % K, co = r / K;
    const float v = (ci < Cin) ? src[((size_t)co * Cin + ci) * K + k] : 0.f;
    const __half h = __float2half_rn(v);
    dh[idx] = h;
    dl[idx] = __float2half_rn(v - __half2float(h));
}

#define NW1 (768*3*128)
#define NW2 (768*3*768)
#define NW3 (768*4*768)
#define NWTOT (NW1 + 3*NW2 + NW3)

__global__ void prep_w_all(const float* __restrict__ w1, const float* __restrict__ w2,
                           const float* __restrict__ w3, const float* __restrict__ w4,
                           const float* __restrict__ w5)
{
    int idx = blockIdx.x * 256 + threadIdx.x;
    if (idx < NW1) { w_split(w1, g_W1h, g_W1l, 80, 128, 3, idx); return; }
    idx -= NW1;
    if (idx < NW2) { w_split(w2, g_W2h, g_W2l, 768, 768, 3, idx); return; }
    idx -= NW2;
    if (idx < NW3) { w_split(w3, g_W3h, g_W3l, 768, 768, 4, idx); return; }
    idx -= NW3;
    if (idx < NW2) { w_split(w4, g_W4h, g_W4l, 768, 768, 3, idx); return; }
    idx -= NW2;
    if (idx < NW2) { w_split(w5, g_W5h, g_W5l, 768, 768, 3, idx); return; }
}

// ============================================================
// Prep: transpose mels [b][80][1024] -> [b][1024][128] halves hi/lo (pad ch).
// ============================================================
__global__ void prep_mels(const float* __restrict__ mels)
{
    __shared__ float ts[80][33];
    const int b = blockIdx.y, t0 = blockIdx.x * 32, tid = threadIdx.x;
    const int tl = tid & 31, cw = tid >> 5;
    for (int c = cw; c < 80; c += 8)
        ts[c][tl] = mels[((size_t)b * 80 + c) * 1024 + t0 + tl];
    __syncthreads();
    const int c0 = (tid & 31) * 4, tw = tid >> 5;
    for (int tt = tw; tt < 32; tt += 8) {
        #pragma unroll
        for (int j = 0; j < 4; j++) {
            const int c = c0 + j;
            const float x = (c < 80) ? ts[c][tt] : 0.f;
            const __half h = __float2half_rn(x);
            const size_t o = ((size_t)b * 1024 + t0 + tt) * 128 + c;
            g_M1h[o] = h;
            g_M1l[o] = __float2half_rn(x - __half2float(h));
        }
    }
}

// ============================================================
// conv6 (1x1, 768->64) + bias + transpose. X is [b][t][768] fp32.
// ============================================================
__global__ __launch_bounds__(256) void conv6_kernel(
    const float* __restrict__ X, const float* __restrict__ W6,
    const float* __restrict__ b6, float* __restrict__ Z)
{
    __shared__ float Xs[64][65];
    __shared__ float Ws[64][65];
    const int tid = threadIdx.x;
    const int b   = blockIdx.y;
    const int t0  = blockIdx.x * 64;
    const int tdx = tid & 15;
    const int ttx = tid >> 4;

    float acc[4][4];
    #pragma unroll
    for (int i = 0; i < 4; i++)
        #pragma unroll
        for (int j = 0; j < 4; j++) acc[i][j] = 0.f;

    const int lt = tid & 63;
    const int lr = tid >> 6;

    for (int c0 = 0; c0 < CCH; c0 += 64) {
        #pragma unroll
        for (int r = 0; r < 16; r++) {
            const int trow = t0 + lr + 4 * r;
            Xs[lt][lr + 4 * r] = (trow < TP)
                ? X[((size_t)b * TP + trow) * CCH + c0 + lt] : 0.f;
            const int d = lr + r * 4;
            Ws[d][lt] = W6[(size_t)d * CCH + c0 + lt];
        }
        __syncthreads();
        #pragma unroll 8
        for (int ci = 0; ci < 64; ci++) {
            float wv[4], x[4];
            #pragma unroll
            for (int i = 0; i < 4; i++) wv[i] = Ws[tdx * 4 + i][ci];
            #pragma unroll
            for (int j = 0; j < 4; j++) x[j] = Xs[ci][ttx * 4 + j];
            #pragma unroll
            for (int i = 0; i < 4; i++)
                #pragma unroll
                for (int j = 0; j < 4; j++)
                    acc[i][j] = fmaf(wv[i], x[j], acc[i][j]);
        }
        __syncthreads();
    }
    #pragma unroll
    for (int i = 0; i < 4; i++) {
        const int d = tdx * 4 + i;
        const float bias = b6[d];
        #pragma unroll
        for (int j = 0; j < 4; j++) {
            const int t = t0 + ttx * 4 + j;
            if (t < TP)
                Z[((size_t)(b * TP + t)) * DDIM + d] = acc[i][j] + bias;
        }
    }
}

// ============================================================
// VQ prep / VQ / finalize (unchanged, validated)
// ============================================================
__global__ void prep_vq(const float* __restrict__ E)
{
    const int e = threadIdx.x;
    float s = 0.f;
    #pragma unroll
    for (int d = 0; d < DDIM; d++) {
        const float v = E[(size_t)e * DDIM + d];
        s = fmaf(v, v, s);
        g_Et[d * MEMB + e] = v;
    }
    g_esq[e] = s;
    g_counts[e] = 0;
}

__global__ __launch_bounds__(256) void vq_kernel(
    const float* __restrict__ Z, const float* __restrict__ E,
    float* __restrict__ out)
{
    __shared__ float zsh[8][64];
    __shared__ float pw[8];
    const int tid  = threadIdx.x;
    const int w    = tid >> 5;
    const int lane = tid & 31;
    const int vec  = blockIdx.x * 8 + w;

    zsh[w][lane]      = Z[(size_t)vec * 64 + lane];
    zsh[w][lane + 32] = Z[(size_t)vec * 64 + lane + 32];
    __syncwarp();

    float best = 3.4e38f;
    int   bidx = 0;
    #pragma unroll
    for (int i = 0; i < 16; i++) {
        const int e = lane + 32 * i;
        float dot = 0.f;
        #pragma unroll
        for (int d = 0; d < 64; d++)
            dot = fmaf(zsh[w][d], g_Et[d * MEMB + e], dot);
        const float dist = g_esq[e] - 2.f * dot;
        if (dist < best) { best = dist; bidx = e; }
    }
    #pragma unroll
    for (int off = 16; off > 0; off >>= 1) {
        const float ob = __shfl_down_sync(0xFFFFFFFFu, best, off);
        const int   oi = __shfl_down_sync(0xFFFFFFFFu, bidx, off);
        if (ob < best || (ob == best && oi < bidx)) { best = ob; bidx = oi; }
    }
    bidx = __shfl_sync(0xFFFFFFFFu, bidx, 0);

    float lsum = 0.f;
    #pragma unroll
    for (int h = 0; h < 2; h++) {
        const int d   = lane + 32 * h;
        const float zv = zsh[w][d];
        const float q  = E[(size_t)bidx * 64 + d];
        out[(size_t)vec * 64 + d] = zv + (q - zv);
        const float diff = zv - q;
        lsum = fmaf(diff, diff, lsum);
    }
    #pragma unroll
    for (int off = 16; off > 0; off >>= 1)
        lsum += __shfl_down_sync(0xFFFFFFFFu, lsum, off);

    if (lane == 0) {
        pw[w] = lsum;
        atomicAdd(&g_counts[bidx], 1);
    }
    __syncthreads();
    if (tid == 0) {
        float s = 0.f;
        #pragma unroll
        for (int i = 0; i < 8; i++) s += pw[i];
        g_partial[blockIdx.x] = s;
    }
}

__global__ __launch_bounds__(1024) void finalize_kernel(float* __restrict__ out)
{
    __shared__ float sh[1024];
    const int tid = threadIdx.x;
    float s = 0.f;
    for (int i = tid; i < NPART; i += 1024) s += g_partial[i];
    sh[tid] = s; __syncthreads();
    for (int off = 512; off > 0; off >>= 1) {
        if (tid < off) sh[tid] += sh[tid + off];
        __syncthreads();
    }
    const float total = sh[0];
    __syncthreads();
    float h = 0.f;
    if (tid < MEMB) {
        const float p = (float)g_counts[tid] / (float)NVEC;
        h = p * logf(p + 1e-10f);
    }
    sh[tid] = h; __syncthreads();
    for (int off = 512; off > 0; off >>= 1) {
        if (tid < off) sh[tid] += sh[tid + off];
        __syncthreads();
    }
    if (tid == 0) {
        out[(size_t)NVEC * DDIM]     = 0.25f * total / (float)((size_t)NVEC * DDIM);
        out[(size_t)NVEC * DDIM + 1] = expf(-sh[0]);
    }
}

// ============================================================
// launch
// ============================================================
extern "C" void kernel_launch(void* const* d_in, const int* in_sizes, int n_in,
                              void* d_out, int out_size)
{
    const float* mels  = (const float*)d_in[0];
    const float* w1    = (const float*)d_in[1];
    const float* w2    = (const float*)d_in[2];
    const float* w3    = (const float*)d_in[3];
    const float* w4    = (const float*)d_in[4];
    const float* w5    = (const float*)d_in[5];
    const float* w6    = (const float*)d_in[6];
    const float* b6    = (const float*)d_in[7];
    const float* gamma = (const float*)d_in[8];
    const float* beta  = (const float*)d_in[9];
    const float* mean  = (const float*)d_in[10];
    const float* var   = (const float*)d_in[11];
    const float* emb   = (const float*)d_in[12];
    float* out = (float*)d_out;

    __half *XAh, *XAl, *XBh, *XBl, *M1h, *M1l;
    __half *W1h, *W1l, *W2h, *W2l, *W3h, *W3l, *W4h, *W4l, *W5h, *W5l;
    float *C5, *zbuf;
    cudaGetSymbolAddress((void**)&XAh, g_XAh);
    cudaGetSymbolAddress((void**)&XAl, g_XAl);
    cudaGetSymbolAddress((void**)&XBh, g_XBh);
    cudaGetSymbolAddress((void**)&XBl, g_XBl);
    cudaGetSymbolAddress((void**)&M1h, g_M1h);
    cudaGetSymbolAddress((void**)&M1l, g_M1l);
    cudaGetSymbolAddress((void**)&C5,  g_C5);
    cudaGetSymbolAddress((void**)&zbuf, g_z);
    cudaGetSymbolAddress((void**)&W1h, g_W1h); cudaGetSymbolAddress((void**)&W1l, g_W1l);
    cudaGetSymbolAddress((void**)&W2h, g_W2h); cudaGetSymbolAddress((void**)&W2l, g_W2l);
    cudaGetSymbolAddress((void**)&W3h, g_W3h); cudaGetSymbolAddress((void**)&W3l, g_W3l);
    cudaGetSymbolAddress((void**)&W4h, g_W4h); cudaGetSymbolAddress((void**)&W4l, g_W4l);
    cudaGetSymbolAddress((void**)&W5h, g_W5h); cudaGetSymbolAddress((void**)&W5l, g_W5l);

    cudaFuncSetAttribute(conv_mma<3,1,0,128,true>,  cudaFuncAttributeMaxDynamicSharedMemorySize, SM_TOT);
    cudaFuncSetAttribute(conv_mma<3,1,1,768,true>,  cudaFuncAttributeMaxDynamicSharedMemorySize, SM_TOT);
    cudaFuncSetAttribute(conv_mma<4,2,1,768,true>,  cudaFuncAttributeMaxDynamicSharedMemorySize, SM_TOT);
    cudaFuncSetAttribute(conv_mma<3,1,1,768,false>, cudaFuncAttributeMaxDynamicSharedMemorySize, SM_TOT);

    // --- prep ---
    prep_w_all<<<(NWTOT + 255)/256, 256>>>(w1, w2, w3, w4, w5);
    prep_mels<<<dim3(32, BATCH), 256>>>(mels);

    // --- conv stack (mma.sync fp16 3-term split, BK=64 async pipeline) ---
    conv_mma<3,1,0,128,true><<<dim3(8, 6, BATCH), 256, SM_TOT>>>(
        M1h, M1l, W1h, W1l, gamma, beta, mean, var,
        XAh, XAl, nullptr, 1024, 1022);
    conv_mma<3,1,1,768,true><<<dim3(8, 6, BATCH), 256, SM_TOT>>>(
        XAh, XAl, W2h, W2l, gamma+CCH, beta+CCH, mean+CCH, var+CCH,
        XBh, XBl, nullptr, 1022, 1022);
    conv_mma<4,2,1,768,true><<<dim3(4, 6, BATCH), 256, SM_TOT>>>(
        XBh, XBl, W3h, W3l, gamma+2*CCH, beta+2*CCH, mean+2*CCH, var+2*CCH,
        XAh, XAl, nullptr, 1022, 511);
    conv_mma<3,1,1,768,true><<<dim3(4, 6, BATCH), 256, SM_TOT>>>(
        XAh, XAl, W4h, W4l, gamma+3*CCH, beta+3*CCH, mean+3*CCH, var+3*CCH,
        XBh, XBl, nullptr, 511, 511);
    conv_mma<3,1,1,768,false><<<dim3(4, 6, BATCH), 256, SM_TOT>>>(
        XBh, XBl, W5h, W5l, gamma+4*CCH, beta+4*CCH, mean+4*CCH, var+4*CCH,
        nullptr, nullptr, C5, 511, 511);

    // --- tail ---
    conv6_kernel<<<dim3(8, BATCH), 256>>>(C5, w6, b6, zbuf);
    prep_vq<<<1, MEMB>>>(emb);
    vq_kernel<<<NPART, 256>>>(zbuf, emb, out);
    finalize_kernel<<<1, 1024>>>(out);
}

// round 7
// speedup vs baseline: 1.5703x; 1.1571x over previous
#include <cuda_runtime.h>
#include <cuda_fp16.h>
#include <math.h>
#include <stdint.h>

// ---------------- problem constants ----------------
#define BATCH 32
#define CCH   768
#define DDIM  64
#define MEMB  512
#define TP    511
#define NVEC  (BATCH * TP)
#define NPART (NVEC / 8)

// ---------------- device scratch (static) ----------------
__device__ __half g_XAh[(size_t)BATCH * 1022 * CCH];
__device__ __half g_XAl[(size_t)BATCH * 1022 * CCH];
__device__ __half g_XBh[(size_t)BATCH * 1022 * CCH];
__device__ __half g_XBl[(size_t)BATCH * 1022 * CCH];
__device__ __half g_M1h[(size_t)BATCH * 1024 * 128];
__device__ __half g_M1l[(size_t)BATCH * 1024 * 128];
__device__ __half g_W1h[768 * 3 * 128], g_W1l[768 * 3 * 128];
__device__ __half g_W2h[768 * 3 * 768], g_W2l[768 * 3 * 768];
__device__ __half g_W3h[768 * 4 * 768], g_W3l[768 * 4 * 768];
__device__ __half g_W4h[768 * 3 * 768], g_W4l[768 * 3 * 768];
__device__ __half g_W5h[768 * 3 * 768], g_W5l[768 * 3 * 768];
__device__ float g_C5[(size_t)BATCH * TP * CCH];     // [b][t][c] fp32
__device__ float g_z[(size_t)NVEC * DDIM];
__device__ float g_Et[DDIM * MEMB];
__device__ float g_esq[MEMB];
__device__ int   g_counts[MEMB];
__device__ float g_partial[NPART];

// ---------------- helpers ----------------
__device__ __forceinline__ uint32_t smem_u32(const void* p) {
    uint32_t a;
    asm("{ .reg .u64 t; cvta.to.shared.u64 t, %1; cvt.u32.u64 %0, t; }"
        : "=r"(a) : "l"(p));
    return a;
}

#define LDMX4(r0, r1, r2, r3, addr) \
    asm volatile("ldmatrix.sync.aligned.m8n8.x4.shared.b16 {%0,%1,%2,%3}, [%4];" \
        : "=r"(r0), "=r"(r1), "=r"(r2), "=r"(r3) : "r"(addr))

__device__ __forceinline__ void mma16816(float* d, const uint32_t* a, const uint32_t* b) {
    asm volatile(
        "mma.sync.aligned.m16n8k16.row.col.f32.f16.f16.f32 "
        "{%0,%1,%2,%3}, {%4,%5,%6,%7}, {%8,%9}, {%0,%1,%2,%3};"
        : "+f"(d[0]), "+f"(d[1]), "+f"(d[2]), "+f"(d[3])
        : "r"(a[0]), "r"(a[1]), "r"(a[2]), "r"(a[3]), "r"(b[0]), "r"(b[1]));
}

__device__ __forceinline__ void cp16(uint32_t dst, const void* src, bool pred) {
    asm volatile("cp.async.cg.shared.global [%0], [%1], 16, %2;"
        :: "r"(dst), "l"(src), "r"(pred ? 16 : 0));
}
#define CP_COMMIT() asm volatile("cp.async.commit_group;" ::: "memory")
#define CP_WAIT0()  asm volatile("cp.async.wait_group 0;" ::: "memory")

// smem: 2 buffers, each = A(20480) + B(20480) = 40960. total 81920 -> 2 CTAs/SM.
// Each tile = 2 plane sheets of 128 rows x 80B (32 halves + 16B pad).
#define RSTR   80
#define PLN    10240
#define ABUF   20480
#define BUFSZ  40960
#define SM_TOT 81920

// ============================================================
// Implicit-GEMM conv1d + BN + ReLU via mma.sync fp16 3-term split.
// BM=128 (co) x BN=128 (t), BK=32. 256 thr, 2 CTAs/SM, warp tile 64x32.
// 2-stage cp.async pipeline, ONE __syncthreads per chunk.
// ============================================================
template<int KTAP, int S, int P, int CIN, bool SPLITOUT>
__global__ void __launch_bounds__(256, 2) conv_mma(
    const __half* __restrict__ Xh, const __half* __restrict__ Xl,
    const __half* __restrict__ Wh, const __half* __restrict__ Wl,
    const float* __restrict__ gam, const float* __restrict__ bet,
    const float* __restrict__ mu,  const float* __restrict__ var,
    __half* __restrict__ Yh, __half* __restrict__ Yl, float* __restrict__ Yf,
    int Tin, int Tout)
{
    extern __shared__ char smem[];
    const uint32_t sb = smem_u32(smem);
    const int tid = threadIdx.x;
    const int lane = tid & 31, w = tid >> 5;
    const int mw = w & 1, nw = w >> 1;          // warp grid: 2(m) x 4(n)
    const int b = blockIdx.z, m0 = blockIdx.y * 128, t0 = blockIdx.x * 128;
    constexpr int Kp = KTAP * CIN;
    constexpr int nchunk = Kp / 32;

    float acc[4][4][4];
    #pragma unroll
    for (int i = 0; i < 4; i++)
        #pragma unroll
        for (int j = 0; j < 4; j++)
            #pragma unroll
            for (int r = 0; r < 4; r++) acc[i][j][r] = 0.f;

    // cp.async loader: 8 x 16B per thread (A: 4, B: 4)
    auto issue = [&](int kc, int buf) {
        const int tap = (kc * 32) / CIN;
        const int ci0 = (kc * 32) % CIN;
        const uint32_t base = sb + buf * BUFSZ;
        #pragma unroll
        for (int i = 0; i < 4; i++) {
            const int idx = i * 256 + tid;          // 0..1023
            const int pl = idx >> 9;                // plane: 0..1
            const int r = (idx >> 2) & 127, seg = idx & 3;
            const __half* W = pl ? Wl : Wh;
            cp16(base + pl * PLN + r * RSTR + seg * 16,
                 W + (size_t)(m0 + r) * Kp + kc * 32 + seg * 8, true);
            const int t_in = (t0 + r) * S + tap - P;
            const bool ok = (t_in >= 0) && (t_in < Tin);
            const int tc = ok ? t_in : 0;
            const __half* X = pl ? Xl : Xh;
            cp16(base + ABUF + pl * PLN + r * RSTR + seg * 16,
                 X + ((size_t)b * Tin + tc) * CIN + ci0 + seg * 8, ok);
        }
    };

    // per-thread ldmatrix base offsets (within one plane sheet)
    const uint32_t aoff = (uint32_t)((mw * 64 + (lane & 15)) * RSTR + (lane >> 4) * 16);
    const uint32_t boff = (uint32_t)((nw * 32 + (lane & 7) + ((lane >> 4) << 3)) * RSTR
                                     + ((lane >> 3) & 1) * 16);

    issue(0, 0);
    CP_COMMIT();

    for (int kc = 0; kc < nchunk; kc++) {
        CP_WAIT0();
        __syncthreads();        // buf[kc] visible; all warps done reading buf[kc-1]
        if (kc + 1 < nchunk) {
            issue(kc + 1, (kc + 1) & 1);    // overlaps with compute below
            CP_COMMIT();
        }
        const uint32_t sa  = sb + (kc & 1) * BUFSZ;
        const uint32_t sbB = sa + ABUF;
        #pragma unroll
        for (int ks = 0; ks < 2; ks++) {
            const int inn = ks * 32;        // 16 halves = 32 bytes
            uint32_t af[2][4][4], bf[2][4][2];
            const uint32_t pb = sbB + boff + inn;
            #pragma unroll
            for (int nc = 0; nc < 2; nc++) {
                LDMX4(bf[0][2*nc][0], bf[0][2*nc][1], bf[0][2*nc+1][0], bf[0][2*nc+1][1],
                      pb + nc * (16 * RSTR));
                LDMX4(bf[1][2*nc][0], bf[1][2*nc][1], bf[1][2*nc+1][0], bf[1][2*nc+1][1],
                      pb + PLN + nc * (16 * RSTR));
            }
            const uint32_t pa = sa + aoff + inn;
            #pragma unroll
            for (int mt = 0; mt < 4; mt++)
                LDMX4(af[0][mt][0], af[0][mt][1], af[0][mt][2], af[0][mt][3],
                      pa + mt * (16 * RSTR));
            #pragma unroll
            for (int mt = 0; mt < 4; mt++)
                LDMX4(af[1][mt][0], af[1][mt][1], af[1][mt][2], af[1][mt][3],
                      pa + PLN + mt * (16 * RSTR));
            // 3-phase ordering: maximal independent MMA chains
            #pragma unroll
            for (int mt = 0; mt < 4; mt++)
                #pragma unroll
                for (int nt = 0; nt < 4; nt++)
                    mma16816(acc[mt][nt], af[0][mt], bf[0][nt]);   // hi*hi
            #pragma unroll
            for (int mt = 0; mt < 4; mt++)
                #pragma unroll
                for (int nt = 0; nt < 4; nt++)
                    mma16816(acc[mt][nt], af[0][mt], bf[1][nt]);   // hi*lo
            #pragma unroll
            for (int mt = 0; mt < 4; mt++)
                #pragma unroll
                for (int nt = 0; nt < 4; nt++)
                    mma16816(acc[mt][nt], af[1][mt], bf[0][nt]);   // lo*hi
        }
    }
    __syncthreads();   // protect smem reuse by epilogue

    // ---------- epilogue: stage [n][m] in smem, BN+ReLU, coalesced stores ----------
    float* eps = (float*)(smem + w * 9216);   // 32 rows x 72 floats (8*9216=73728<81920)
    #pragma unroll
    for (int mt = 0; mt < 4; mt++)
        #pragma unroll
        for (int nt = 0; nt < 4; nt++)
            #pragma unroll
            for (int r = 0; r < 4; r++) {
                const int nl = nt * 8 + 2 * (lane & 3) + (r & 1);
                const int ml = mt * 16 + (lane >> 2) + ((r >> 1) << 3);
                eps[nl * 72 + ml] = acc[mt][nt][r];
            }
    __syncwarp();

    const int cg = m0 + mw * 64 + lane * 2;
    const float inv0 = gam[cg] * rsqrtf(var[cg] + 1e-5f);
    const float sh0  = bet[cg] - mu[cg] * inv0;
    const float inv1 = gam[cg + 1] * rsqrtf(var[cg + 1] + 1e-5f);
    const float sh1  = bet[cg + 1] - mu[cg + 1] * inv1;

    #pragma unroll 4
    for (int rn = 0; rn < 32; rn++) {
        const int t = t0 + nw * 32 + rn;
        if (t < Tout) {
            float v0 = fmaf(eps[rn * 72 + lane * 2], inv0, sh0);
            float v1 = fmaf(eps[rn * 72 + lane * 2 + 1], inv1, sh1);
            v0 = v0 > 0.f ? v0 : 0.f;
            v1 = v1 > 0.f ? v1 : 0.f;
            const size_t o = ((size_t)b * Tout + t) * CCH + cg;
            if (SPLITOUT) {
                const __half h0 = __float2half_rn(v0);
                const __half h1 = __float2half_rn(v1);
                const __half l0 = __float2half_rn(v0 - __half2float(h0));
                const __half l1 = __float2half_rn(v1 - __half2float(h1));
                *(__half2*)(Yh + o) = __halves2half2(h0, h1);
                *(__half2*)(Yl + o) = __halves2half2(l0, l1);
            } else {
                *(float2*)(Yf + o) = make_float2(v0, v1);
            }
        }
    }
}

// ============================================================
// Fused weight prep (one launch): [co][ci][k] -> [co][tap*Cpad+ci], hi/lo fp16.
// ============================================================
__device__ __forceinline__ void w_split(const float* __restrict__ src,
                                        __half* dh, __half* dl,
                                        int Cin, int Cpad, int K, int idx)
{
    const int ci = idx % Cpad;
    const int r  = idx / Cpad;
    const int k  = r % K, co = r / K;
    const float v = (ci < Cin) ? src[((size_t)co * Cin + ci) * K + k] : 0.f;
    const __half h = __float2half_rn(v);
    dh[idx] = h;
    dl[idx] = __float2half_rn(v - __half2float(h));
}

#define NW1 (768*3*128)
#define NW2 (768*3*768)
#define NW3 (768*4*768)
#define NWTOT (NW1 + 3*NW2 + NW3)

__global__ void prep_w_all(const float* __restrict__ w1, const float* __restrict__ w2,
                           const float* __restrict__ w3, const float* __restrict__ w4,
                           const float* __restrict__ w5)
{
    int idx = blockIdx.x * 256 + threadIdx.x;
    if (idx < NW1) { w_split(w1, g_W1h, g_W1l, 80, 128, 3, idx); return; }
    idx -= NW1;
    if (idx < NW2) { w_split(w2, g_W2h, g_W2l, 768, 768, 3, idx); return; }
    idx -= NW2;
    if (idx < NW3) { w_split(w3, g_W3h, g_W3l, 768, 768, 4, idx); return; }
    idx -= NW3;
    if (idx < NW2) { w_split(w4, g_W4h, g_W4l, 768, 768, 3, idx); return; }
    idx -= NW2;
    if (idx < NW2) { w_split(w5, g_W5h, g_W5l, 768, 768, 3, idx); return; }
}

// ============================================================
// Prep: transpose mels [b][80][1024] -> [b][1024][128] halves hi/lo (pad ch).
// ============================================================
__global__ void prep_mels(const float* __restrict__ mels)
{
    __shared__ float ts[80][33];
    const int b = blockIdx.y, t0 = blockIdx.x * 32, tid = threadIdx.x;
    const int tl = tid & 31, cw = tid >> 5;
    for (int c = cw; c < 80; c += 8)
        ts[c][tl] = mels[((size_t)b * 80 + c) * 1024 + t0 + tl];
    __syncthreads();
    const int c0 = (tid & 31) * 4, tw = tid >> 5;
    for (int tt = tw; tt < 32; tt += 8) {
        #pragma unroll
        for (int j = 0; j < 4; j++) {
            const int c = c0 + j;
            const float x = (c < 80) ? ts[c][tt] : 0.f;
            const __half h = __float2half_rn(x);
            const size_t o = ((size_t)b * 1024 + t0 + tt) * 128 + c;
            g_M1h[o] = h;
            g_M1l[o] = __float2half_rn(x - __half2float(h));
        }
    }
}

// ============================================================
// conv6 (1x1, 768->64) + bias + transpose. X is [b][t][768] fp32.
// ============================================================
__global__ __launch_bounds__(256) void conv6_kernel(
    const float* __restrict__ X, const float* __restrict__ W6,
    const float* __restrict__ b6, float* __restrict__ Z)
{
    __shared__ float Xs[64][65];
    __shared__ float Ws[64][65];
    const int tid = threadIdx.x;
    const int b   = blockIdx.y;
    const int t0  = blockIdx.x * 64;
    const int tdx = tid & 15;
    const int ttx = tid >> 4;

    float acc[4][4];
    #pragma unroll
    for (int i = 0; i < 4; i++)
        #pragma unroll
        for (int j = 0; j < 4; j++) acc[i][j] = 0.f;

    const int lt = tid & 63;
    const int lr = tid >> 6;

    for (int c0 = 0; c0 < CCH; c0 += 64) {
        #pragma unroll
        for (int r = 0; r < 16; r++) {
            const int trow = t0 + lr + 4 * r;
            Xs[lt][lr + 4 * r] = (trow < TP)
                ? X[((size_t)b * TP + trow) * CCH + c0 + lt] : 0.f;
            const int d = lr + r * 4;
            Ws[d][lt] = W6[(size_t)d * CCH + c0 + lt];
        }
        __syncthreads();
        #pragma unroll 8
        for (int ci = 0; ci < 64; ci++) {
            float wv[4], x[4];
            #pragma unroll
            for (int i = 0; i < 4; i++) wv[i] = Ws[tdx * 4 + i][ci];
            #pragma unroll
            for (int j = 0; j < 4; j++) x[j] = Xs[ci][ttx * 4 + j];
            #pragma unroll
            for (int i = 0; i < 4; i++)
                #pragma unroll
                for (int j = 0; j < 4; j++)
                    acc[i][j] = fmaf(wv[i], x[j], acc[i][j]);
        }
        __syncthreads();
    }
    #pragma unroll
    for (int i = 0; i < 4; i++) {
        const int d = tdx * 4 + i;
        const float bias = b6[d];
        #pragma unroll
        for (int j = 0; j < 4; j++) {
            const int t = t0 + ttx * 4 + j;
            if (t < TP)
                Z[((size_t)(b * TP + t)) * DDIM + d] = acc[i][j] + bias;
        }
    }
}

// ============================================================
// VQ prep / VQ / finalize (unchanged, validated)
// ============================================================
__global__ void prep_vq(const float* __restrict__ E)
{
    const int e = threadIdx.x;
    float s = 0.f;
    #pragma unroll
    for (int d = 0; d < DDIM; d++) {
        const float v = E[(size_t)e * DDIM + d];
        s = fmaf(v, v, s);
        g_Et[d * MEMB + e] = v;
    }
    g_esq[e] = s;
    g_counts[e] = 0;
}

__global__ __launch_bounds__(256) void vq_kernel(
    const float* __restrict__ Z, const float* __restrict__ E,
    float* __restrict__ out)
{
    __shared__ float zsh[8][64];
    __shared__ float pw[8];
    const int tid  = threadIdx.x;
    const int w    = tid >> 5;
    const int lane = tid & 31;
    const int vec  = blockIdx.x * 8 + w;

    zsh[w][lane]      = Z[(size_t)vec * 64 + lane];
    zsh[w][lane + 32] = Z[(size_t)vec * 64 + lane + 32];
    __syncwarp();

    float best = 3.4e38f;
    int   bidx = 0;
    #pragma unroll
    for (int i = 0; i < 16; i++) {
        const int e = lane + 32 * i;
        float dot = 0.f;
        #pragma unroll
        for (int d = 0; d < 64; d++)
            dot = fmaf(zsh[w][d], g_Et[d * MEMB + e], dot);
        const float dist = g_esq[e] - 2.f * dot;
        if (dist < best) { best = dist; bidx = e; }
    }
    #pragma unroll
    for (int off = 16; off > 0; off >>= 1) {
        const float ob = __shfl_down_sync(0xFFFFFFFFu, best, off);
        const int   oi = __shfl_down_sync(0xFFFFFFFFu, bidx, off);
        if (ob < best || (ob == best && oi < bidx)) { best = ob; bidx = oi; }
    }
    bidx = __shfl_sync(0xFFFFFFFFu, bidx, 0);

    float lsum = 0.f;
    #pragma unroll
    for (int h = 0; h < 2; h++) {
        const int d   = lane + 32 * h;
        const float zv = zsh[w][d];
        const float q  = E[(size_t)bidx * 64 + d];
        out[(size_t)vec * 64 + d] = zv + (q - zv);
        const float diff = zv - q;
        lsum = fmaf(diff, diff, lsum);
    }
    #pragma unroll
    for (int off = 16; off > 0; off >>= 1)
        lsum += __shfl_down_sync(0xFFFFFFFFu, lsum, off);

    if (lane == 0) {
        pw[w] = lsum;
        atomicAdd(&g_counts[bidx], 1);
    }
    __syncthreads();
    if (tid == 0) {
        float s = 0.f;
        #pragma unroll
        for (int i = 0; i < 8; i++) s += pw[i];
        g_partial[blockIdx.x] = s;
    }
}

__global__ __launch_bounds__(1024) void finalize_kernel(float* __restrict__ out)
{
    __shared__ float sh[1024];
    const int tid = threadIdx.x;
    float s = 0.f;
    for (int i = tid; i < NPART; i += 1024) s += g_partial[i];
    sh[tid] = s; __syncthreads();
    for (int off = 512; off > 0; off >>= 1) {
        if (tid < off) sh[tid] += sh[tid + off];
        __syncthreads();
    }
    const float total = sh[0];
    __syncthreads();
    float h = 0.f;
    if (tid < MEMB) {
        const float p = (float)g_counts[tid] / (float)NVEC;
        h = p * logf(p + 1e-10f);
    }
    sh[tid] = h; __syncthreads();
    for (int off = 512; off > 0; off >>= 1) {
        if (tid < off) sh[tid] += sh[tid + off];
        __syncthreads();
    }
    if (tid == 0) {
        out[(size_t)NVEC * DDIM]     = 0.25f * total / (float)((size_t)NVEC * DDIM);
        out[(size_t)NVEC * DDIM + 1] = expf(-sh[0]);
    }
}

// ============================================================
// launch
// ============================================================
extern "C" void kernel_launch(void* const* d_in, const int* in_sizes, int n_in,
                              void* d_out, int out_size)
{
    const float* mels  = (const float*)d_in[0];
    const float* w1    = (const float*)d_in[1];
    const float* w2    = (const float*)d_in[2];
    const float* w3    = (const float*)d_in[3];
    const float* w4    = (const float*)d_in[4];
    const float* w5    = (const float*)d_in[5];
    const float* w6    = (const float*)d_in[6];
    const float* b6    = (const float*)d_in[7];
    const float* gamma = (const float*)d_in[8];
    const float* beta  = (const float*)d_in[9];
    const float* mean  = (const float*)d_in[10];
    const float* var   = (const float*)d_in[11];
    const float* emb   = (const float*)d_in[12];
    float* out = (float*)d_out;

    __half *XAh, *XAl, *XBh, *XBl, *M1h, *M1l;
    __half *W1h, *W1l, *W2h, *W2l, *W3h, *W3l, *W4h, *W4l, *W5h, *W5l;
    float *C5, *zbuf;
    cudaGetSymbolAddress((void**)&XAh, g_XAh);
    cudaGetSymbolAddress((void**)&XAl, g_XAl);
    cudaGetSymbolAddress((void**)&XBh, g_XBh);
    cudaGetSymbolAddress((void**)&XBl, g_XBl);
    cudaGetSymbolAddress((void**)&M1h, g_M1h);
    cudaGetSymbolAddress((void**)&M1l, g_M1l);
    cudaGetSymbolAddress((void**)&C5,  g_C5);
    cudaGetSymbolAddress((void**)&zbuf, g_z);
    cudaGetSymbolAddress((void**)&W1h, g_W1h); cudaGetSymbolAddress((void**)&W1l, g_W1l);
    cudaGetSymbolAddress((void**)&W2h, g_W2h); cudaGetSymbolAddress((void**)&W2l, g_W2l);
    cudaGetSymbolAddress((void**)&W3h, g_W3h); cudaGetSymbolAddress((void**)&W3l, g_W3l);
    cudaGetSymbolAddress((void**)&W4h, g_W4h); cudaGetSymbolAddress((void**)&W4l, g_W4l);
    cudaGetSymbolAddress((void**)&W5h, g_W5h); cudaGetSymbolAddress((void**)&W5l, g_W5l);

    cudaFuncSetAttribute(conv_mma<3,1,0,128,true>,  cudaFuncAttributeMaxDynamicSharedMemorySize, SM_TOT);
    cudaFuncSetAttribute(conv_mma<3,1,1,768,true>,  cudaFuncAttributeMaxDynamicSharedMemorySize, SM_TOT);
    cudaFuncSetAttribute(conv_mma<4,2,1,768,true>,  cudaFuncAttributeMaxDynamicSharedMemorySize, SM_TOT);
    cudaFuncSetAttribute(conv_mma<3,1,1,768,false>, cudaFuncAttributeMaxDynamicSharedMemorySize, SM_TOT);

    // --- prep ---
    prep_w_all<<<(NWTOT + 255)/256, 256>>>(w1, w2, w3, w4, w5);
    prep_mels<<<dim3(32, BATCH), 256>>>(mels);

    // --- conv stack (mma.sync fp16 3-term split, BK=32, 2 CTAs/SM) ---
    conv_mma<3,1,0,128,true><<<dim3(8, 6, BATCH), 256, BUFSZ*2>>>(
        M1h, M1l, W1h, W1l, gamma, beta, mean, var,
        XAh, XAl, nullptr, 1024, 1022);
    conv_mma<3,1,1,768,true><<<dim3(8, 6, BATCH), 256, BUFSZ*2>>>(
        XAh, XAl, W2h, W2l, gamma+CCH, beta+CCH, mean+CCH, var+CCH,
        XBh, XBl, nullptr, 1022, 1022);
    conv_mma<4,2,1,768,true><<<dim3(4, 6, BATCH), 256, BUFSZ*2>>>(
        XBh, XBl, W3h, W3l, gamma+2*CCH, beta+2*CCH, mean+2*CCH, var+2*CCH,
        XAh, XAl, nullptr, 1022, 511);
    conv_mma<3,1,1,768,true><<<dim3(4, 6, BATCH), 256, BUFSZ*2>>>(
        XAh, XAl, W4h, W4l, gamma+3*CCH, beta+3*CCH, mean+3*CCH, var+3*CCH,
        XBh, XBl, nullptr, 511, 511);
    conv_mma<3,1,1,768,false><<<dim3(4, 6, BATCH), 256, BUFSZ*2>>>(
        XBh, XBl, W5h, W5l, gamma+4*CCH, beta+4*CCH, mean+4*CCH, var+4*CCH,
        nullptr, nullptr, C5, 511, 511);

    // --- tail ---
    conv6_kernel<<<dim3(8, BATCH), 256>>>(C5, w6, b6, zbuf);
    prep_vq<<<1, MEMB>>>(emb);
    vq_kernel<<<NPART, 256>>>(zbuf, emb, out);
    finalize_kernel<<<1, 1024>>>(out);
}

// round 8
// speedup vs baseline: 1.7289x; 1.1010x over previous
#include <cuda_runtime.h>
#include <cuda_fp16.h>
#include <math.h>
#include <stdint.h>

// ---------------- problem constants ----------------
#define BATCH 32
#define CCH   768
#define DDIM  64
#define MEMB  512
#define TP    511
#define NVEC  (BATCH * TP)
#define NPART (NVEC / 8)

// ---------------- device scratch (static) ----------------
__device__ __half g_XAh[(size_t)BATCH * 1022 * CCH];
__device__ __half g_XAl[(size_t)BATCH * 1022 * CCH];
__device__ __half g_XBh[(size_t)BATCH * 1022 * CCH];
__device__ __half g_XBl[(size_t)BATCH * 1022 * CCH];
__device__ __half g_M1h[(size_t)BATCH * 1024 * 128];
__device__ __half g_M1l[(size_t)BATCH * 1024 * 128];
__device__ __half g_W1h[768 * 3 * 128], g_W1l[768 * 3 * 128];
__device__ __half g_W2h[768 * 3 * 768], g_W2l[768 * 3 * 768];
__device__ __half g_W3h[768 * 4 * 768], g_W3l[768 * 4 * 768];
__device__ __half g_W4h[768 * 3 * 768], g_W4l[768 * 3 * 768];
__device__ __half g_W5h[768 * 3 * 768], g_W5l[768 * 3 * 768];
__device__ float g_C5[(size_t)BATCH * TP * CCH];     // [b][t][c] fp32
__device__ float g_z[(size_t)NVEC * DDIM];
__device__ float g_Et[DDIM * MEMB];
__device__ float g_esq[MEMB];
__device__ int   g_counts[MEMB];
__device__ float g_partial[NPART];

// ---------------- helpers ----------------
__device__ __forceinline__ uint32_t smem_u32(const void* p) {
    uint32_t a;
    asm("{ .reg .u64 t; cvta.to.shared.u64 t, %1; cvt.u32.u64 %0, t; }"
        : "=r"(a) : "l"(p));
    return a;
}

#define LDMX4(r0, r1, r2, r3, addr) \
    asm volatile("ldmatrix.sync.aligned.m8n8.x4.shared.b16 {%0,%1,%2,%3}, [%4];" \
        : "=r"(r0), "=r"(r1), "=r"(r2), "=r"(r3) : "r"(addr))

__device__ __forceinline__ void mma16816(float* d, const uint32_t* a, const uint32_t* b) {
    asm volatile(
        "mma.sync.aligned.m16n8k16.row.col.f32.f16.f16.f32 "
        "{%0,%1,%2,%3}, {%4,%5,%6,%7}, {%8,%9}, {%0,%1,%2,%3};"
        : "+f"(d[0]), "+f"(d[1]), "+f"(d[2]), "+f"(d[3])
        : "r"(a[0]), "r"(a[1]), "r"(a[2]), "r"(a[3]), "r"(b[0]), "r"(b[1]));
}

__device__ __forceinline__ void cp16(uint32_t dst, const void* src, bool pred) {
    asm volatile("cp.async.cg.shared.global [%0], [%1], 16, %2;"
        :: "r"(dst), "l"(src), "r"(pred ? 16 : 0));
}
#define CP_COMMIT() asm volatile("cp.async.commit_group;" ::: "memory")
#define CP_WAIT1()  asm volatile("cp.async.wait_group 1;" ::: "memory")
#define CP_WAIT0()  asm volatile("cp.async.wait_group 0;" ::: "memory")

// smem: 3 stages, each = A(16384) + B(16384) = 32768. total 98304 -> 2 CTAs/SM.
// Rows are 64B (32 halves), NO padding; bank conflicts avoided by XOR swizzle:
//   16B-slot s stored at slot s ^ ((row>>1)&3).
#define PLN    8192          // one plane sheet: 128 rows x 64B
#define ABUF   16384         // A = 2 plane sheets
#define BUFSZ  32768
#define NSTAGE 3
#define SM_TOT 98304

// ============================================================
// Implicit-GEMM conv1d + BN + ReLU via mma.sync fp16 3-term split.
// BM=128 (co) x BN=128 (t), BK=32. 256 thr, 2 CTAs/SM, warp tile 64x32.
// 3-stage cp.async pipeline (swizzled, pad-free smem).
// ============================================================
template<int KTAP, int S, int P, int CIN, bool SPLITOUT>
__global__ void __launch_bounds__(256, 2) conv_mma(
    const __half* __restrict__ Xh, const __half* __restrict__ Xl,
    const __half* __restrict__ Wh, const __half* __restrict__ Wl,
    const float* __restrict__ gam, const float* __restrict__ bet,
    const float* __restrict__ mu,  const float* __restrict__ var,
    __half* __restrict__ Yh, __half* __restrict__ Yl, float* __restrict__ Yf,
    int Tin, int Tout)
{
    extern __shared__ char smem[];
    const uint32_t sb = smem_u32(smem);
    const int tid = threadIdx.x;
    const int lane = tid & 31, w = tid >> 5;
    const int mw = w & 1, nw = w >> 1;          // warp grid: 2(m) x 4(n)
    const int b = blockIdx.z, m0 = blockIdx.y * 128, t0 = blockIdx.x * 128;
    constexpr int Kp = KTAP * CIN;
    constexpr int nchunk = Kp / 32;

    float acc[4][4][4];
    #pragma unroll
    for (int i = 0; i < 4; i++)
        #pragma unroll
        for (int j = 0; j < 4; j++)
            #pragma unroll
            for (int r = 0; r < 4; r++) acc[i][j][r] = 0.f;

    // cp.async loader: 8 x 16B per thread (A: 4, B: 4), swizzled dst slots.
    auto issue = [&](int kc, int st) {
        const int tap = (kc * 32) / CIN;
        const int ci0 = (kc * 32) % CIN;
        const uint32_t base = sb + st * BUFSZ;
        #pragma unroll
        for (int i = 0; i < 4; i++) {
            const int idx = i * 256 + tid;          // 0..1023
            const int pl = idx >> 9;                // plane: 0..1
            const int r = (idx >> 2) & 127, seg = idx & 3;
            const int sseg = seg ^ ((r >> 1) & 3);  // swizzle
            const __half* W = pl ? Wl : Wh;
            cp16(base + pl * PLN + r * 64 + sseg * 16,
                 W + (size_t)(m0 + r) * Kp + kc * 32 + seg * 8, true);
            const int t_in = (t0 + r) * S + tap - P;
            const bool ok = (t_in >= 0) && (t_in < Tin);
            const int tc = ok ? t_in : 0;
            const __half* X = pl ? Xl : Xh;
            cp16(base + ABUF + pl * PLN + r * 64 + sseg * 16,
                 X + ((size_t)b * Tin + tc) * CIN + ci0 + seg * 8, ok);
        }
    };

    // per-thread ldmatrix row bases and swizzle constants
    const int r_a = mw * 64 + (lane & 15);               // +16*mt later (preserves swz)
    const uint32_t aswz = (uint32_t)((r_a >> 1) & 3);
    const uint32_t abase = (uint32_t)(r_a * 64);
    const uint32_t as0 = (uint32_t)(lane >> 4);          // seg 0/1
    const int r_b = nw * 32 + (lane & 7) + ((lane >> 4) << 3);  // +16*nc later
    const uint32_t bswz = (uint32_t)((r_b >> 1) & 3);
    const uint32_t bbase = (uint32_t)(r_b * 64);
    const uint32_t bs0 = (uint32_t)((lane >> 3) & 1);

    issue(0, 0);
    CP_COMMIT();
    issue(1, 1);
    CP_COMMIT();

    for (int kc = 0; kc < nchunk; kc++) {
        if (kc + 1 < nchunk) CP_WAIT1(); else CP_WAIT0();
        __syncthreads();        // stage kc visible; stage (kc-1) free for reuse
        if (kc + 2 < nchunk) {
            issue(kc + 2, (kc + 2) % NSTAGE);
            CP_COMMIT();
        }
        const uint32_t sa  = sb + (kc % NSTAGE) * BUFSZ;
        const uint32_t sbB = sa + ABUF;
        #pragma unroll
        for (int ks = 0; ks < 2; ks++) {
            uint32_t af[2][4][4], bf[2][4][2];
            const uint32_t bslot = ((bs0 + 2 * ks) ^ bswz) * 16;
            #pragma unroll
            for (int nc = 0; nc < 2; nc++) {
                LDMX4(bf[0][2*nc][0], bf[0][2*nc][1], bf[0][2*nc+1][0], bf[0][2*nc+1][1],
                      sbB + bbase + nc * 1024 + bslot);
                LDMX4(bf[1][2*nc][0], bf[1][2*nc][1], bf[1][2*nc+1][0], bf[1][2*nc+1][1],
                      sbB + PLN + bbase + nc * 1024 + bslot);
            }
            const uint32_t aslot = ((as0 + 2 * ks) ^ aswz) * 16;
            #pragma unroll
            for (int mt = 0; mt < 4; mt++)
                LDMX4(af[0][mt][0], af[0][mt][1], af[0][mt][2], af[0][mt][3],
                      sa + abase + mt * 1024 + aslot);
            #pragma unroll
            for (int mt = 0; mt < 4; mt++)
                LDMX4(af[1][mt][0], af[1][mt][1], af[1][mt][2], af[1][mt][3],
                      sa + PLN + abase + mt * 1024 + aslot);
            // 3-phase ordering: maximal independent MMA chains
            #pragma unroll
            for (int mt = 0; mt < 4; mt++)
                #pragma unroll
                for (int nt = 0; nt < 4; nt++)
                    mma16816(acc[mt][nt], af[0][mt], bf[0][nt]);   // hi*hi
            #pragma unroll
            for (int mt = 0; mt < 4; mt++)
                #pragma unroll
                for (int nt = 0; nt < 4; nt++)
                    mma16816(acc[mt][nt], af[0][mt], bf[1][nt]);   // hi*lo
            #pragma unroll
            for (int mt = 0; mt < 4; mt++)
                #pragma unroll
                for (int nt = 0; nt < 4; nt++)
                    mma16816(acc[mt][nt], af[1][mt], bf[0][nt]);   // lo*hi
        }
    }
    __syncthreads();   // protect smem reuse by epilogue

    // ---------- epilogue: stage [n][m] in smem, BN+ReLU, coalesced stores ----------
    float* eps = (float*)(smem + w * 9216);   // 32 rows x 72 floats (8*9216=73728<98304)
    #pragma unroll
    for (int mt = 0; mt < 4; mt++)
        #pragma unroll
        for (int nt = 0; nt < 4; nt++)
            #pragma unroll
            for (int r = 0; r < 4; r++) {
                const int nl = nt * 8 + 2 * (lane & 3) + (r & 1);
                const int ml = mt * 16 + (lane >> 2) + ((r >> 1) << 3);
                eps[nl * 72 + ml] = acc[mt][nt][r];
            }
    __syncwarp();

    const int cg = m0 + mw * 64 + lane * 2;
    const float inv0 = gam[cg] * rsqrtf(var[cg] + 1e-5f);
    const float sh0  = bet[cg] - mu[cg] * inv0;
    const float inv1 = gam[cg + 1] * rsqrtf(var[cg + 1] + 1e-5f);
    const float sh1  = bet[cg + 1] - mu[cg + 1] * inv1;

    #pragma unroll 4
    for (int rn = 0; rn < 32; rn++) {
        const int t = t0 + nw * 32 + rn;
        if (t < Tout) {
            float v0 = fmaf(eps[rn * 72 + lane * 2], inv0, sh0);
            float v1 = fmaf(eps[rn * 72 + lane * 2 + 1], inv1, sh1);
            v0 = v0 > 0.f ? v0 : 0.f;
            v1 = v1 > 0.f ? v1 : 0.f;
            const size_t o = ((size_t)b * Tout + t) * CCH + cg;
            if (SPLITOUT) {
                const __half h0 = __float2half_rn(v0);
                const __half h1 = __float2half_rn(v1);
                const __half l0 = __float2half_rn(v0 - __half2float(h0));
                const __half l1 = __float2half_rn(v1 - __half2float(h1));
                *(__half2*)(Yh + o) = __halves2half2(h0, h1);
                *(__half2*)(Yl + o) = __halves2half2(l0, l1);
            } else {
                *(float2*)(Yf + o) = make_float2(v0, v1);
            }
        }
    }
}

// ============================================================
// Fused weight prep (one launch): [co][ci][k] -> [co][tap*Cpad+ci], hi/lo fp16.
// ============================================================
__device__ __forceinline__ void w_split(const float* __restrict__ src,
                                        __half* dh, __half* dl,
                                        int Cin, int Cpad, int K, int idx)
{
    const int ci = idx % Cpad;
    const int r  = idx / Cpad;
    const int k  = r % K, co = r / K;
    const float v = (ci < Cin) ? src[((size_t)co * Cin + ci) * K + k] : 0.f;
    const __half h = __float2half_rn(v);
    dh[idx] = h;
    dl[idx] = __float2half_rn(v - __half2float(h));
}

#define NW1 (768*3*128)
#define NW2 (768*3*768)
#define NW3 (768*4*768)
#define NWTOT (NW1 + 3*NW2 + NW3)

__global__ void prep_w_all(const float* __restrict__ w1, const float* __restrict__ w2,
                           const float* __restrict__ w3, const float* __restrict__ w4,
                           const float* __restrict__ w5)
{
    int idx = blockIdx.x * 256 + threadIdx.x;
    if (idx < NW1) { w_split(w1, g_W1h, g_W1l, 80, 128, 3, idx); return; }
    idx -= NW1;
    if (idx < NW2) { w_split(w2, g_W2h, g_W2l, 768, 768, 3, idx); return; }
    idx -= NW2;
    if (idx < NW3) { w_split(w3, g_W3h, g_W3l, 768, 768, 4, idx); return; }
    idx -= NW3;
    if (idx < NW2) { w_split(w4, g_W4h, g_W4l, 768, 768, 3, idx); return; }
    idx -= NW2;
    if (idx < NW2) { w_split(w5, g_W5h, g_W5l, 768, 768, 3, idx); return; }
}

// ============================================================
// Prep: transpose mels [b][80][1024] -> [b][1024][128] halves hi/lo (pad ch).
// ============================================================
__global__ void prep_mels(const float* __restrict__ mels)
{
    __shared__ float ts[80][33];
    const int b = blockIdx.y, t0 = blockIdx.x * 32, tid = threadIdx.x;
    const int tl = tid & 31, cw = tid >> 5;
    for (int c = cw; c < 80; c += 8)
        ts[c][tl] = mels[((size_t)b * 80 + c) * 1024 + t0 + tl];
    __syncthreads();
    const int c0 = (tid & 31) * 4, tw = tid >> 5;
    for (int tt = tw; tt < 32; tt += 8) {
        #pragma unroll
        for (int j = 0; j < 4; j++) {
            const int c = c0 + j;
            const float x = (c < 80) ? ts[c][tt] : 0.f;
            const __half h = __float2half_rn(x);
            const size_t o = ((size_t)b * 1024 + t0 + tt) * 128 + c;
            g_M1h[o] = h;
            g_M1l[o] = __float2half_rn(x - __half2float(h));
        }
    }
}

// ============================================================
// conv6 (1x1, 768->64) + bias + transpose. X is [b][t][768] fp32.
// Tile: 64 d x 32 t per CTA -> 512 CTAs (better SM coverage).
// ============================================================
__global__ __launch_bounds__(256) void conv6_kernel(
    const float* __restrict__ X, const float* __restrict__ W6,
    const float* __restrict__ b6, float* __restrict__ Z)
{
    __shared__ float Xs[64][33];   // [ci][t]
    __shared__ float Ws[64][65];   // [d][ci]
    const int tid = threadIdx.x;
    const int b   = blockIdx.y;
    const int t0  = blockIdx.x * 32;
    const int tdx = tid & 15;      // d group (4 d each)
    const int ttx = tid >> 4;      // t group (2 t each)

    float acc[4][2];
    #pragma unroll
    for (int i = 0; i < 4; i++) { acc[i][0] = 0.f; acc[i][1] = 0.f; }

    const int lc = tid & 63;       // ci within 64
    const int lr = tid >> 6;       // 0..3

    for (int c0 = 0; c0 < CCH; c0 += 64) {
        #pragma unroll
        for (int r = 0; r < 8; r++) {
            const int t = lr + 4 * r;             // 0..31
            const int trow = t0 + t;
            Xs[lc][t] = (trow < TP)
                ? X[((size_t)b * TP + trow) * CCH + c0 + lc] : 0.f;
        }
        #pragma unroll
        for (int r = 0; r < 16; r++) {
            const int d = lr + r * 4;
            Ws[d][lc] = W6[(size_t)d * CCH + c0 + lc];
        }
        __syncthreads();
        #pragma unroll 8
        for (int ci = 0; ci < 64; ci++) {
            float wv[4], x[2];
            #pragma unroll
            for (int i = 0; i < 4; i++) wv[i] = Ws[tdx * 4 + i][ci];
            x[0] = Xs[ci][ttx * 2];
            x[1] = Xs[ci][ttx * 2 + 1];
            #pragma unroll
            for (int i = 0; i < 4; i++) {
                acc[i][0] = fmaf(wv[i], x[0], acc[i][0]);
                acc[i][1] = fmaf(wv[i], x[1], acc[i][1]);
            }
        }
        __syncthreads();
    }
    #pragma unroll
    for (int i = 0; i < 4; i++) {
        const int d = tdx * 4 + i;
        const float bias = b6[d];
        #pragma unroll
        for (int j = 0; j < 2; j++) {
            const int t = t0 + ttx * 2 + j;
            if (t < TP)
                Z[((size_t)(b * TP + t)) * DDIM + d] = acc[i][j] + bias;
        }
    }
}

// ============================================================
// VQ prep (8 blocks) / VQ / finalize
// ============================================================
__global__ void prep_vq(const float* __restrict__ E)
{
    const int e = blockIdx.x * 64 + threadIdx.x;   // 8 x 64 = 512
    float s = 0.f;
    #pragma unroll
    for (int d = 0; d < DDIM; d++) {
        const float v = E[(size_t)e * DDIM + d];
        s = fmaf(v, v, s);
        g_Et[d * MEMB + e] = v;
    }
    g_esq[e] = s;
    g_counts[e] = 0;
}

__global__ __launch_bounds__(256) void vq_kernel(
    const float* __restrict__ Z, const float* __restrict__ E,
    float* __restrict__ out)
{
    __shared__ float zsh[8][64];
    __shared__ float pw[8];
    const int tid  = threadIdx.x;
    const int w    = tid >> 5;
    const int lane = tid & 31;
    const int vec  = blockIdx.x * 8 + w;

    zsh[w][lane]      = Z[(size_t)vec * 64 + lane];
    zsh[w][lane + 32] = Z[(size_t)vec * 64 + lane + 32];
    __syncwarp();

    float best = 3.4e38f;
    int   bidx = 0;
    #pragma unroll
    for (int i = 0; i < 16; i++) {
        const int e = lane + 32 * i;
        float dot = 0.f;
        #pragma unroll
        for (int d = 0; d < 64; d++)
            dot = fmaf(zsh[w][d], g_Et[d * MEMB + e], dot);
        const float dist = g_esq[e] - 2.f * dot;
        if (dist < best) { best = dist; bidx = e; }
    }
    #pragma unroll
    for (int off = 16; off > 0; off >>= 1) {
        const float ob = __shfl_down_sync(0xFFFFFFFFu, best, off);
        const int   oi = __shfl_down_sync(0xFFFFFFFFu, bidx, off);
        if (ob < best || (ob == best && oi < bidx)) { best = ob; bidx = oi; }
    }
    bidx = __shfl_sync(0xFFFFFFFFu, bidx, 0);

    float lsum = 0.f;
    #pragma unroll
    for (int h = 0; h < 2; h++) {
        const int d   = lane + 32 * h;
        const float zv = zsh[w][d];
        const float q  = E[(size_t)bidx * 64 + d];
        out[(size_t)vec * 64 + d] = zv + (q - zv);
        const float diff = zv - q;
        lsum = fmaf(diff, diff, lsum);
    }
    #pragma unroll
    for (int off = 16; off > 0; off >>= 1)
        lsum += __shfl_down_sync(0xFFFFFFFFu, lsum, off);

    if (lane == 0) {
        pw[w] = lsum;
        atomicAdd(&g_counts[bidx], 1);
    }
    __syncthreads();
    if (tid == 0) {
        float s = 0.f;
        #pragma unroll
        for (int i = 0; i < 8; i++) s += pw[i];
        g_partial[blockIdx.x] = s;
    }
}

__global__ __launch_bounds__(1024) void finalize_kernel(float* __restrict__ out)
{
    __shared__ float sh[1024];
    const int tid = threadIdx.x;
    float s = 0.f;
    for (int i = tid; i < NPART; i += 1024) s += g_partial[i];
    sh[tid] = s; __syncthreads();
    for (int off = 512; off > 0; off >>= 1) {
        if (tid < off) sh[tid] += sh[tid + off];
        __syncthreads();
    }
    const float total = sh[0];
    __syncthreads();
    float h = 0.f;
    if (tid < MEMB) {
        const float p = (float)g_counts[tid] / (float)NVEC;
        h = p * logf(p + 1e-10f);
    }
    sh[tid] = h; __syncthreads();
    for (int off = 512; off > 0; off >>= 1) {
        if (tid < off) sh[tid] += sh[tid + off];
        __syncthreads();
    }
    if (tid == 0) {
        out[(size_t)NVEC * DDIM]     = 0.25f * total / (float)((size_t)NVEC * DDIM);
        out[(size_t)NVEC * DDIM + 1] = expf(-sh[0]);
    }
}

// ============================================================
// launch
// ============================================================
extern "C" void kernel_launch(void* const* d_in, const int* in_sizes, int n_in,
                              void* d_out, int out_size)
{
    const float* mels  = (const float*)d_in[0];
    const float* w1    = (const float*)d_in[1];
    const float* w2    = (const float*)d_in[2];
    const float* w3    = (const float*)d_in[3];
    const float* w4    = (const float*)d_in[4];
    const float* w5    = (const float*)d_in[5];
    const float* w6    = (const float*)d_in[6];
    const float* b6    = (const float*)d_in[7];
    const float* gamma = (const float*)d_in[8];
    const float* beta  = (const float*)d_in[9];
    const float* mean  = (const float*)d_in[10];
    const float* var   = (const float*)d_in[11];
    const float* emb   = (const float*)d_in[12];
    float* out = (float*)d_out;

    __half *XAh, *XAl, *XBh, *XBl, *M1h, *M1l;
    __half *W1h, *W1l, *W2h, *W2l, *W3h, *W3l, *W4h, *W4l, *W5h, *W5l;
    float *C5, *zbuf;
    cudaGetSymbolAddress((void**)&XAh, g_XAh);
    cudaGetSymbolAddress((void**)&XAl, g_XAl);
    cudaGetSymbolAddress((void**)&XBh, g_XBh);
    cudaGetSymbolAddress((void**)&XBl, g_XBl);
    cudaGetSymbolAddress((void**)&M1h, g_M1h);
    cudaGetSymbolAddress((void**)&M1l, g_M1l);
    cudaGetSymbolAddress((void**)&C5,  g_C5);
    cudaGetSymbolAddress((void**)&zbuf, g_z);
    cudaGetSymbolAddress((void**)&W1h, g_W1h); cudaGetSymbolAddress((void**)&W1l, g_W1l);
    cudaGetSymbolAddress((void**)&W2h, g_W2h); cudaGetSymbolAddress((void**)&W2l, g_W2l);
    cudaGetSymbolAddress((void**)&W3h, g_W3h); cudaGetSymbolAddress((void**)&W3l, g_W3l);
    cudaGetSymbolAddress((void**)&W4h, g_W4h); cudaGetSymbolAddress((void**)&W4l, g_W4l);
    cudaGetSymbolAddress((void**)&W5h, g_W5h); cudaGetSymbolAddress((void**)&W5l, g_W5l);

    cudaFuncSetAttribute(conv_mma<3,1,0,128,true>,  cudaFuncAttributeMaxDynamicSharedMemorySize, SM_TOT);
    cudaFuncSetAttribute(conv_mma<3,1,1,768,true>,  cudaFuncAttributeMaxDynamicSharedMemorySize, SM_TOT);
    cudaFuncSetAttribute(conv_mma<4,2,1,768,true>,  cudaFuncAttributeMaxDynamicSharedMemorySize, SM_TOT);
    cudaFuncSetAttribute(conv_mma<3,1,1,768,false>, cudaFuncAttributeMaxDynamicSharedMemorySize, SM_TOT);

    // --- prep ---
    prep_w_all<<<(NWTOT + 255)/256, 256>>>(w1, w2, w3, w4, w5);
    prep_mels<<<dim3(32, BATCH), 256>>>(mels);

    // --- conv stack (mma.sync fp16 3-term split, BK=32, 3-stage, 2 CTAs/SM) ---
    conv_mma<3,1,0,128,true><<<dim3(8, 6, BATCH), 256, SM_TOT>>>(
        M1h, M1l, W1h, W1l, gamma, beta, mean, var,
        XAh, XAl, nullptr, 1024, 1022);
    conv_mma<3,1,1,768,true><<<dim3(8, 6, BATCH), 256, SM_TOT>>>(
        XAh, XAl, W2h, W2l, gamma+CCH, beta+CCH, mean+CCH, var+CCH,
        XBh, XBl, nullptr, 1022, 1022);
    conv_mma<4,2,1,768,true><<<dim3(4, 6, BATCH), 256, SM_TOT>>>(
        XBh, XBl, W3h, W3l, gamma+2*CCH, beta+2*CCH, mean+2*CCH, var+2*CCH,
        XAh, XAl, nullptr, 1022, 511);
    conv_mma<3,1,1,768,true><<<dim3(4, 6, BATCH), 256, SM_TOT>>>(
        XAh, XAl, W4h, W4l, gamma+3*CCH, beta+3*CCH, mean+3*CCH, var+3*CCH,
        XBh, XBl, nullptr, 511, 511);
    conv_mma<3,1,1,768,false><<<dim3(4, 6, BATCH), 256, SM_TOT>>>(
        XBh, XBl, W5h, W5l, gamma+4*CCH, beta+4*CCH, mean+4*CCH, var+4*CCH,
        nullptr, nullptr, C5, 511, 511);

    // --- tail ---
    conv6_kernel<<<dim3(16, BATCH), 256>>>(C5, w6, b6, zbuf);
    prep_vq<<<8, 64>>>(emb);
    vq_kernel<<<NPART, 256>>>(zbuf, emb, out);
    finalize_kernel<<<1, 1024>>>(out);
}

// round 9
// speedup vs baseline: 1.8243x; 1.0552x over previous
#include <cuda_runtime.h>
#include <cuda_fp16.h>
#include <math.h>
#include <stdint.h>

// ---------------- problem constants ----------------
#define BATCH 32
#define CCH   768
#define DDIM  64
#define MEMB  512
#define TP    511
#define NVEC  (BATCH * TP)
#define NPART (NVEC / 8)

// ---------------- device scratch (static) ----------------
__device__ __half g_XAh[(size_t)BATCH * 1022 * CCH];
__device__ __half g_XAl[(size_t)BATCH * 1022 * CCH];
__device__ __half g_XBh[(size_t)BATCH * 1022 * CCH];
__device__ __half g_XBl[(size_t)BATCH * 1022 * CCH];
__device__ __half g_M1h[(size_t)BATCH * 1024 * 128];
__device__ __half g_M1l[(size_t)BATCH * 1024 * 128];
__device__ __half g_W1h[768 * 3 * 128], g_W1l[768 * 3 * 128];
__device__ __half g_W2h[768 * 3 * 768], g_W2l[768 * 3 * 768];
__device__ __half g_W3h[768 * 4 * 768], g_W3l[768 * 4 * 768];
__device__ __half g_W4h[768 * 3 * 768], g_W4l[768 * 3 * 768];
__device__ __half g_W5h[768 * 3 * 768], g_W5l[768 * 3 * 768];
__device__ float g_C5[(size_t)BATCH * TP * CCH];     // [b][t][c] fp32
__device__ float g_z[(size_t)NVEC * DDIM];
__device__ float g_Et[DDIM * MEMB];
__device__ float g_esq[MEMB];
__device__ int   g_counts[MEMB];
__device__ float g_partial[NPART];

// ---------------- helpers ----------------
__device__ __forceinline__ uint32_t smem_u32(const void* p) {
    uint32_t a;
    asm("{ .reg .u64 t; cvta.to.shared.u64 t, %1; cvt.u32.u64 %0, t; }"
        : "=r"(a) : "l"(p));
    return a;
}

#define LDMX4(r0, r1, r2, r3, addr) \
    asm volatile("ldmatrix.sync.aligned.m8n8.x4.shared.b16 {%0,%1,%2,%3}, [%4];" \
        : "=r"(r0), "=r"(r1), "=r"(r2), "=r"(r3) : "r"(addr))

__device__ __forceinline__ void mma16816(float* d, const uint32_t* a, const uint32_t* b) {
    asm volatile(
        "mma.sync.aligned.m16n8k16.row.col.f32.f16.f16.f32 "
        "{%0,%1,%2,%3}, {%4,%5,%6,%7}, {%8,%9}, {%0,%1,%2,%3};"
        : "+f"(d[0]), "+f"(d[1]), "+f"(d[2]), "+f"(d[3])
        : "r"(a[0]), "r"(a[1]), "r"(a[2]), "r"(a[3]), "r"(b[0]), "r"(b[1]));
}

__device__ __forceinline__ void cp16(uint32_t dst, const void* src, bool pred) {
    asm volatile("cp.async.cg.shared.global [%0], [%1], 16, %2;"
        :: "r"(dst), "l"(src), "r"(pred ? 16 : 0));
}
#define CP_COMMIT() asm volatile("cp.async.commit_group;" ::: "memory")
#define CP_WAIT1()  asm volatile("cp.async.wait_group 1;" ::: "memory")
#define CP_WAIT0()  asm volatile("cp.async.wait_group 0;" ::: "memory")

// smem: 3 stages, each = A(16384) + B(16384) = 32768. total 98304 -> 2 CTAs/SM.
// Rows 64B (32 halves), no padding; XOR swizzle: slot s stored at s ^ ((row>>1)&3).
#define PLN    8192          // one plane sheet: 128 rows x 64B
#define ABUF   16384
#define BUFSZ  32768
#define NSTAGE 3
#define SM_TOT 98304

// ============================================================
// Implicit-GEMM conv1d + BN + ReLU via mma.sync fp16 3-term split.
// BM=128 (co) x BN=128 (t), BK=32. 128 thr (4 warps, 2m x 2n),
// warp tile 64x64 (1.5x less smem frag traffic). 2 CTAs/SM, 3-stage pipeline.
// ============================================================
template<int KTAP, int S, int P, int CIN, bool SPLITOUT>
__global__ void __launch_bounds__(128, 2) conv_mma(
    const __half* __restrict__ Xh, const __half* __restrict__ Xl,
    const __half* __restrict__ Wh, const __half* __restrict__ Wl,
    const float* __restrict__ gam, const float* __restrict__ bet,
    const float* __restrict__ mu,  const float* __restrict__ var,
    __half* __restrict__ Yh, __half* __restrict__ Yl, float* __restrict__ Yf,
    int Tin, int Tout)
{
    extern __shared__ char smem[];
    const uint32_t sb = smem_u32(smem);
    const int tid = threadIdx.x;
    const int lane = tid & 31, w = tid >> 5;   // 4 warps
    const int mw = w & 1, nw = w >> 1;         // warp grid: 2(m) x 2(n), tile 64x64
    const int b = blockIdx.z, m0 = blockIdx.y * 128, t0 = blockIdx.x * 128;
    constexpr int Kp = KTAP * CIN;
    constexpr int nchunk = Kp / 32;

    float acc[4][8][4];
    #pragma unroll
    for (int i = 0; i < 4; i++)
        #pragma unroll
        for (int j = 0; j < 8; j++)
            #pragma unroll
            for (int r = 0; r < 4; r++) acc[i][j][r] = 0.f;

    // cp.async loader: 16 x 16B per thread (A: 8, B: 8), swizzled dst slots.
    auto issue = [&](int kc, int st) {
        const int tap = (kc * 32) / CIN;
        const int ci0 = (kc * 32) % CIN;
        const uint32_t base = sb + st * BUFSZ;
        #pragma unroll
        for (int i = 0; i < 8; i++) {
            const int idx = i * 128 + tid;          // 0..1023
            const int pl = idx >> 9;                // plane: 0..1
            const int r = (idx >> 2) & 127, seg = idx & 3;
            const int sseg = seg ^ ((r >> 1) & 3);  // swizzle
            const __half* W = pl ? Wl : Wh;
            cp16(base + pl * PLN + r * 64 + sseg * 16,
                 W + (size_t)(m0 + r) * Kp + kc * 32 + seg * 8, true);
            const int t_in = (t0 + r) * S + tap - P;
            const bool ok = (t_in >= 0) && (t_in < Tin);
            const int tc = ok ? t_in : 0;
            const __half* X = pl ? Xl : Xh;
            cp16(base + ABUF + pl * PLN + r * 64 + sseg * 16,
                 X + ((size_t)b * Tin + tc) * CIN + ci0 + seg * 8, ok);
        }
    };

    // per-thread ldmatrix row bases and swizzle constants
    const int r_a = mw * 64 + (lane & 15);               // +16*mt (preserves swz)
    const uint32_t aswz = (uint32_t)((r_a >> 1) & 3);
    const uint32_t abase = (uint32_t)(r_a * 64);
    const uint32_t as0 = (uint32_t)(lane >> 4);
    const int r_b = nw * 64 + (lane & 7) + ((lane >> 4) << 3);  // +16*nc
    const uint32_t bswz = (uint32_t)((r_b >> 1) & 3);
    const uint32_t bbase = (uint32_t)(r_b * 64);
    const uint32_t bs0 = (uint32_t)((lane >> 3) & 1);

    issue(0, 0);
    CP_COMMIT();
    issue(1, 1);
    CP_COMMIT();

    for (int kc = 0; kc < nchunk; kc++) {
        if (kc + 1 < nchunk) CP_WAIT1(); else CP_WAIT0();
        __syncthreads();        // stage kc visible; stage (kc-1) free for reuse
        if (kc + 2 < nchunk) {
            issue(kc + 2, (kc + 2) % NSTAGE);
            CP_COMMIT();
        }
        const uint32_t sa  = sb + (kc % NSTAGE) * BUFSZ;
        const uint32_t sbB = sa + ABUF;
        #pragma unroll
        for (int ks = 0; ks < 2; ks++) {
            uint32_t af[2][4][4], bf[2][8][2];
            const uint32_t bslot = ((bs0 + 2 * ks) ^ bswz) * 16;
            #pragma unroll
            for (int nc = 0; nc < 4; nc++) {
                LDMX4(bf[0][2*nc][0], bf[0][2*nc][1], bf[0][2*nc+1][0], bf[0][2*nc+1][1],
                      sbB + bbase + nc * 1024 + bslot);
                LDMX4(bf[1][2*nc][0], bf[1][2*nc][1], bf[1][2*nc+1][0], bf[1][2*nc+1][1],
                      sbB + PLN + bbase + nc * 1024 + bslot);
            }
            const uint32_t aslot = ((as0 + 2 * ks) ^ aswz) * 16;
            #pragma unroll
            for (int mt = 0; mt < 4; mt++)
                LDMX4(af[0][mt][0], af[0][mt][1], af[0][mt][2], af[0][mt][3],
                      sa + abase + mt * 1024 + aslot);
            #pragma unroll
            for (int mt = 0; mt < 4; mt++)
                LDMX4(af[1][mt][0], af[1][mt][1], af[1][mt][2], af[1][mt][3],
                      sa + PLN + abase + mt * 1024 + aslot);
            // 3-phase ordering: 32 independent accumulator chains per phase
            #pragma unroll
            for (int mt = 0; mt < 4; mt++)
                #pragma unroll
                for (int nt = 0; nt < 8; nt++)
                    mma16816(acc[mt][nt], af[0][mt], bf[0][nt]);   // hi*hi
            #pragma unroll
            for (int mt = 0; mt < 4; mt++)
                #pragma unroll
                for (int nt = 0; nt < 8; nt++)
                    mma16816(acc[mt][nt], af[0][mt], bf[1][nt]);   // hi*lo
            #pragma unroll
            for (int mt = 0; mt < 4; mt++)
                #pragma unroll
                for (int nt = 0; nt < 8; nt++)
                    mma16816(acc[mt][nt], af[1][mt], bf[0][nt]);   // lo*hi
        }
    }
    __syncthreads();   // protect smem reuse by epilogue

    // ---------- epilogue: stage [t][co] in smem, BN+ReLU, coalesced stores ----------
    float* eps = (float*)(smem + w * 18432);   // 64 rows x 72 floats (4*18432=73728)
    #pragma unroll
    for (int mt = 0; mt < 4; mt++)
        #pragma unroll
        for (int nt = 0; nt < 8; nt++)
            #pragma unroll
            for (int r = 0; r < 4; r++) {
                const int nl = nt * 8 + 2 * (lane & 3) + (r & 1);        // 0..63 (t)
                const int ml = mt * 16 + (lane >> 2) + ((r >> 1) << 3);  // 0..63 (co)
                eps[nl * 72 + ml] = acc[mt][nt][r];
            }
    __syncwarp();

    const int cg = m0 + mw * 64 + lane * 2;
    const float inv0 = gam[cg] * rsqrtf(var[cg] + 1e-5f);
    const float sh0  = bet[cg] - mu[cg] * inv0;
    const float inv1 = gam[cg + 1] * rsqrtf(var[cg + 1] + 1e-5f);
    const float sh1  = bet[cg + 1] - mu[cg + 1] * inv1;

    #pragma unroll 4
    for (int rn = 0; rn < 64; rn++) {
        const int t = t0 + nw * 64 + rn;
        if (t < Tout) {
            float v0 = fmaf(eps[rn * 72 + lane * 2], inv0, sh0);
            float v1 = fmaf(eps[rn * 72 + lane * 2 + 1], inv1, sh1);
            v0 = v0 > 0.f ? v0 : 0.f;
            v1 = v1 > 0.f ? v1 : 0.f;
            const size_t o = ((size_t)b * Tout + t) * CCH + cg;
            if (SPLITOUT) {
                const __half h0 = __float2half_rn(v0);
                const __half h1 = __float2half_rn(v1);
                const __half l0 = __float2half_rn(v0 - __half2float(h0));
                const __half l1 = __float2half_rn(v1 - __half2float(h1));
                *(__half2*)(Yh + o) = __halves2half2(h0, h1);
                *(__half2*)(Yl + o) = __halves2half2(l0, l1);
            } else {
                *(float2*)(Yf + o) = make_float2(v0, v1);
            }
        }
    }
}

// ============================================================
// Fused weight prep (one launch): [co][ci][k] -> [co][tap*Cpad+ci], hi/lo fp16.
// ============================================================
__device__ __forceinline__ void w_split(const float* __restrict__ src,
                                        __half* dh, __half* dl,
                                        int Cin, int Cpad, int K, int idx)
{
    const int ci = idx % Cpad;
    const int r  = idx / Cpad;
    const int k  = r % K, co = r / K;
    const float v = (ci < Cin) ? src[((size_t)co * Cin + ci) * K + k] : 0.f;
    const __half h = __float2half_rn(v);
    dh[idx] = h;
    dl[idx] = __float2half_rn(v - __half2float(h));
}

#define NW1 (768*3*128)
#define NW2 (768*3*768)
#define NW3 (768*4*768)
#define NWTOT (NW1 + 3*NW2 + NW3)

__global__ void prep_w_all(const float* __restrict__ w1, const float* __restrict__ w2,
                           const float* __restrict__ w3, const float* __restrict__ w4,
                           const float* __restrict__ w5)
{
    int idx = blockIdx.x * 256 + threadIdx.x;
    if (idx < NW1) { w_split(w1, g_W1h, g_W1l, 80, 128, 3, idx); return; }
    idx -= NW1;
    if (idx < NW2) { w_split(w2, g_W2h, g_W2l, 768, 768, 3, idx); return; }
    idx -= NW2;
    if (idx < NW3) { w_split(w3, g_W3h, g_W3l, 768, 768, 4, idx); return; }
    idx -= NW3;
    if (idx < NW2) { w_split(w4, g_W4h, g_W4l, 768, 768, 3, idx); return; }
    idx -= NW2;
    if (idx < NW2) { w_split(w5, g_W5h, g_W5l, 768, 768, 3, idx); return; }
}

// ============================================================
// Prep: transpose mels [b][80][1024] -> [b][1024][128] halves hi/lo (pad ch).
// ============================================================
__global__ void prep_mels(const float* __restrict__ mels)
{
    __shared__ float ts[80][33];
    const int b = blockIdx.y, t0 = blockIdx.x * 32, tid = threadIdx.x;
    const int tl = tid & 31, cw = tid >> 5;
    for (int c = cw; c < 80; c += 8)
        ts[c][tl] = mels[((size_t)b * 80 + c) * 1024 + t0 + tl];
    __syncthreads();
    const int c0 = (tid & 31) * 4, tw = tid >> 5;
    for (int tt = tw; tt < 32; tt += 8) {
        #pragma unroll
        for (int j = 0; j < 4; j++) {
            const int c = c0 + j;
            const float x = (c < 80) ? ts[c][tt] : 0.f;
            const __half h = __float2half_rn(x);
            const size_t o = ((size_t)b * 1024 + t0 + tt) * 128 + c;
            g_M1h[o] = h;
            g_M1l[o] = __float2half_rn(x - __half2float(h));
        }
    }
}

// ============================================================
// conv6 (1x1, 768->64) + bias + transpose. X is [b][t][768] fp32.
// ============================================================
__global__ __launch_bounds__(256) void conv6_kernel(
    const float* __restrict__ X, const float* __restrict__ W6,
    const float* __restrict__ b6, float* __restrict__ Z)
{
    __shared__ float Xs[64][33];   // [ci][t]
    __shared__ float Ws[64][65];   // [d][ci]
    const int tid = threadIdx.x;
    const int b   = blockIdx.y;
    const int t0  = blockIdx.x * 32;
    const int tdx = tid & 15;      // d group (4 d each)
    const int ttx = tid >> 4;      // t group (2 t each)

    float acc[4][2];
    #pragma unroll
    for (int i = 0; i < 4; i++) { acc[i][0] = 0.f; acc[i][1] = 0.f; }

    const int lc = tid & 63;
    const int lr = tid >> 6;

    for (int c0 = 0; c0 < CCH; c0 += 64) {
        #pragma unroll
        for (int r = 0; r < 8; r++) {
            const int t = lr + 4 * r;
            const int trow = t0 + t;
            Xs[lc][t] = (trow < TP)
                ? X[((size_t)b * TP + trow) * CCH + c0 + lc] : 0.f;
        }
        #pragma unroll
        for (int r = 0; r < 16; r++) {
            const int d = lr + r * 4;
            Ws[d][lc] = W6[(size_t)d * CCH + c0 + lc];
        }
        __syncthreads();
        #pragma unroll 8
        for (int ci = 0; ci < 64; ci++) {
            float wv[4], x[2];
            #pragma unroll
            for (int i = 0; i < 4; i++) wv[i] = Ws[tdx * 4 + i][ci];
            x[0] = Xs[ci][ttx * 2];
            x[1] = Xs[ci][ttx * 2 + 1];
            #pragma unroll
            for (int i = 0; i < 4; i++) {
                acc[i][0] = fmaf(wv[i], x[0], acc[i][0]);
                acc[i][1] = fmaf(wv[i], x[1], acc[i][1]);
            }
        }
        __syncthreads();
    }
    #pragma unroll
    for (int i = 0; i < 4; i++) {
        const int d = tdx * 4 + i;
        const float bias = b6[d];
        #pragma unroll
        for (int j = 0; j < 2; j++) {
            const int t = t0 + ttx * 2 + j;
            if (t < TP)
                Z[((size_t)(b * TP + t)) * DDIM + d] = acc[i][j] + bias;
        }
    }
}

// ============================================================
// VQ prep (8 blocks) / VQ / finalize
// ============================================================
__global__ void prep_vq(const float* __restrict__ E)
{
    const int e = blockIdx.x * 64 + threadIdx.x;
    float s = 0.f;
    #pragma unroll
    for (int d = 0; d < DDIM; d++) {
        const float v = E[(size_t)e * DDIM + d];
        s = fmaf(v, v, s);
        g_Et[d * MEMB + e] = v;
    }
    g_esq[e] = s;
    g_counts[e] = 0;
}

__global__ __launch_bounds__(256) void vq_kernel(
    const float* __restrict__ Z, const float* __restrict__ E,
    float* __restrict__ out)
{
    __shared__ float zsh[8][64];
    __shared__ float pw[8];
    const int tid  = threadIdx.x;
    const int w    = tid >> 5;
    const int lane = tid & 31;
    const int vec  = blockIdx.x * 8 + w;

    zsh[w][lane]      = Z[(size_t)vec * 64 + lane];
    zsh[w][lane + 32] = Z[(size_t)vec * 64 + lane + 32];
    __syncwarp();

    float best = 3.4e38f;
    int   bidx = 0;
    #pragma unroll
    for (int i = 0; i < 16; i++) {
        const int e = lane + 32 * i;
        float dot = 0.f;
        #pragma unroll
        for (int d = 0; d < 64; d++)
            dot = fmaf(zsh[w][d], g_Et[d * MEMB + e], dot);
        const float dist = g_esq[e] - 2.f * dot;
        if (dist < best) { best = dist; bidx = e; }
    }
    #pragma unroll
    for (int off = 16; off > 0; off >>= 1) {
        const float ob = __shfl_down_sync(0xFFFFFFFFu, best, off);
        const int   oi = __shfl_down_sync(0xFFFFFFFFu, bidx, off);
        if (ob < best || (ob == best && oi < bidx)) { best = ob; bidx = oi; }
    }
    bidx = __shfl_sync(0xFFFFFFFFu, bidx, 0);

    float lsum = 0.f;
    #pragma unroll
    for (int h = 0; h < 2; h++) {
        const int d   = lane + 32 * h;
        const float zv = zsh[w][d];
        const float q  = E[(size_t)bidx * 64 + d];
        out[(size_t)vec * 64 + d] = zv + (q - zv);
        const float diff = zv - q;
        lsum = fmaf(diff, diff, lsum);
    }
    #pragma unroll
    for (int off = 16; off > 0; off >>= 1)
        lsum += __shfl_down_sync(0xFFFFFFFFu, lsum, off);

    if (lane == 0) {
        pw[w] = lsum;
        atomicAdd(&g_counts[bidx], 1);
    }
    __syncthreads();
    if (tid == 0) {
        float s = 0.f;
        #pragma unroll
        for (int i = 0; i < 8; i++) s += pw[i];
        g_partial[blockIdx.x] = s;
    }
}

__global__ __launch_bounds__(1024) void finalize_kernel(float* __restrict__ out)
{
    __shared__ float sh[1024];
    const int tid = threadIdx.x;
    float s = 0.f;
    for (int i = tid; i < NPART; i += 1024) s += g_partial[i];
    sh[tid] = s; __syncthreads();
    for (int off = 512; off > 0; off >>= 1) {
        if (tid < off) sh[tid] += sh[tid + off];
        __syncthreads();
    }
    const float total = sh[0];
    __syncthreads();
    float h = 0.f;
    if (tid < MEMB) {
        const float p = (float)g_counts[tid] / (float)NVEC;
        h = p * logf(p + 1e-10f);
    }
    sh[tid] = h; __syncthreads();
    for (int off = 512; off > 0; off >>= 1) {
        if (tid < off) sh[tid] += sh[tid + off];
        __syncthreads();
    }
    if (tid == 0) {
        out[(size_t)NVEC * DDIM]     = 0.25f * total / (float)((size_t)NVEC * DDIM);
        out[(size_t)NVEC * DDIM + 1] = expf(-sh[0]);
    }
}

// ============================================================
// launch
// ============================================================
extern "C" void kernel_launch(void* const* d_in, const int* in_sizes, int n_in,
                              void* d_out, int out_size)
{
    const float* mels  = (const float*)d_in[0];
    const float* w1    = (const float*)d_in[1];
    const float* w2    = (const float*)d_in[2];
    const float* w3    = (const float*)d_in[3];
    const float* w4    = (const float*)d_in[4];
    const float* w5    = (const float*)d_in[5];
    const float* w6    = (const float*)d_in[6];
    const float* b6    = (const float*)d_in[7];
    const float* gamma = (const float*)d_in[8];
    const float* beta  = (const float*)d_in[9];
    const float* mean  = (const float*)d_in[10];
    const float* var   = (const float*)d_in[11];
    const float* emb   = (const float*)d_in[12];
    float* out = (float*)d_out;

    __half *XAh, *XAl, *XBh, *XBl, *M1h, *M1l;
    __half *W1h, *W1l, *W2h, *W2l, *W3h, *W3l, *W4h, *W4l, *W5h, *W5l;
    float *C5, *zbuf;
    cudaGetSymbolAddress((void**)&XAh, g_XAh);
    cudaGetSymbolAddress((void**)&XAl, g_XAl);
    cudaGetSymbolAddress((void**)&XBh, g_XBh);
    cudaGetSymbolAddress((void**)&XBl, g_XBl);
    cudaGetSymbolAddress((void**)&M1h, g_M1h);
    cudaGetSymbolAddress((void**)&M1l, g_M1l);
    cudaGetSymbolAddress((void**)&C5,  g_C5);
    cudaGetSymbolAddress((void**)&zbuf, g_z);
    cudaGetSymbolAddress((void**)&W1h, g_W1h); cudaGetSymbolAddress((void**)&W1l, g_W1l);
    cudaGetSymbolAddress((void**)&W2h, g_W2h); cudaGetSymbolAddress((void**)&W2l, g_W2l);
    cudaGetSymbolAddress((void**)&W3h, g_W3h); cudaGetSymbolAddress((void**)&W3l, g_W3l);
    cudaGetSymbolAddress((void**)&W4h, g_W4h); cudaGetSymbolAddress((void**)&W4l, g_W4l);
    cudaGetSymbolAddress((void**)&W5h, g_W5h); cudaGetSymbolAddress((void**)&W5l, g_W5l);

    cudaFuncSetAttribute(conv_mma<3,1,0,128,true>,  cudaFuncAttributeMaxDynamicSharedMemorySize, SM_TOT);
    cudaFuncSetAttribute(conv_mma<3,1,1,768,true>,  cudaFuncAttributeMaxDynamicSharedMemorySize, SM_TOT);
    cudaFuncSetAttribute(conv_mma<4,2,1,768,true>,  cudaFuncAttributeMaxDynamicSharedMemorySize, SM_TOT);
    cudaFuncSetAttribute(conv_mma<3,1,1,768,false>, cudaFuncAttributeMaxDynamicSharedMemorySize, SM_TOT);

    // --- prep ---
    prep_w_all<<<(NWTOT + 255)/256, 256>>>(w1, w2, w3, w4, w5);
    prep_mels<<<dim3(32, BATCH), 256>>>(mels);

    // --- conv stack (fp16 3-term split, 64x64 warp tile, 2 CTAs/SM) ---
    conv_mma<3,1,0,128,true><<<dim3(8, 6, BATCH), 128, SM_TOT>>>(
        M1h, M1l, W1h, W1l, gamma, beta, mean, var,
        XAh, XAl, nullptr, 1024, 1022);
    conv_mma<3,1,1,768,true><<<dim3(8, 6, BATCH), 128, SM_TOT>>>(
        XAh, XAl, W2h, W2l, gamma+CCH, beta+CCH, mean+CCH, var+CCH,
        XBh, XBl, nullptr, 1022, 1022);
    conv_mma<4,2,1,768,true><<<dim3(4, 6, BATCH), 128, SM_TOT>>>(
        XBh, XBl, W3h, W3l, gamma+2*CCH, beta+2*CCH, mean+2*CCH, var+2*CCH,
        XAh, XAl, nullptr, 1022, 511);
    conv_mma<3,1,1,768,true><<<dim3(4, 6, BATCH), 128, SM_TOT>>>(
        XAh, XAl, W4h, W4l, gamma+3*CCH, beta+3*CCH, mean+3*CCH, var+3*CCH,
        XBh, XBl, nullptr, 511, 511);
    conv_mma<3,1,1,768,false><<<dim3(4, 6, BATCH), 128, SM_TOT>>>(
        XBh, XBl, W5h, W5l, gamma+4*CCH, beta+4*CCH, mean+4*CCH, var+4*CCH,
        nullptr, nullptr, C5, 511, 511);

    // --- tail ---
    conv6_kernel<<<dim3(16, BATCH), 256>>>(C5, w6, b6, zbuf);
    prep_vq<<<8, 64>>>(emb);
    vq_kernel<<<NPART, 256>>>(zbuf, emb, out);
    finalize_kernel<<<1, 1024>>>(out);
}

// round 10
// speedup vs baseline: 1.8323x; 1.0044x over previous
#include <cuda_runtime.h>
#include <cuda_fp16.h>
#include <math.h>
#include <stdint.h>

// ---------------- problem constants ----------------
#define BATCH 32
#define CCH   768
#define DDIM  64
#define MEMB  512
#define TP    511
#define NVEC  (BATCH * TP)
#define NPART 512              // conv6_vq grid: 16 x 32

// ---------------- device scratch (static) ----------------
__device__ __half g_XAh[(size_t)BATCH * 1022 * CCH];
__device__ __half g_XAl[(size_t)BATCH * 1022 * CCH];
__device__ __half g_XBh[(size_t)BATCH * 1022 * CCH];
__device__ __half g_XBl[(size_t)BATCH * 1022 * CCH];
__device__ __half g_M1h[(size_t)BATCH * 1024 * 128];
__device__ __half g_M1l[(size_t)BATCH * 1024 * 128];
__device__ __half g_W1h[768 * 3 * 128], g_W1l[768 * 3 * 128];
__device__ __half g_W2h[768 * 3 * 768], g_W2l[768 * 3 * 768];
__device__ __half g_W3h[768 * 4 * 768], g_W3l[768 * 4 * 768];
__device__ __half g_W4h[768 * 3 * 768], g_W4l[768 * 3 * 768];
__device__ __half g_W5h[768 * 3 * 768], g_W5l[768 * 3 * 768];
__device__ float g_C5[(size_t)BATCH * TP * CCH];     // [b][t][c] fp32
__device__ float g_Et[DDIM * MEMB];
__device__ float g_esq[MEMB];
__device__ int   g_counts[MEMB];
__device__ float g_partial[NPART];

// ---------------- helpers ----------------
__device__ __forceinline__ uint32_t smem_u32(const void* p) {
    uint32_t a;
    asm("{ .reg .u64 t; cvta.to.shared.u64 t, %1; cvt.u32.u64 %0, t; }"
        : "=r"(a) : "l"(p));
    return a;
}

#define LDMX4(r0, r1, r2, r3, addr) \
    asm volatile("ldmatrix.sync.aligned.m8n8.x4.shared.b16 {%0,%1,%2,%3}, [%4];" \
        : "=r"(r0), "=r"(r1), "=r"(r2), "=r"(r3) : "r"(addr))

__device__ __forceinline__ void mma16816(float* d, const uint32_t* a, const uint32_t* b) {
    asm volatile(
        "mma.sync.aligned.m16n8k16.row.col.f32.f16.f16.f32 "
        "{%0,%1,%2,%3}, {%4,%5,%6,%7}, {%8,%9}, {%0,%1,%2,%3};"
        : "+f"(d[0]), "+f"(d[1]), "+f"(d[2]), "+f"(d[3])
        : "r"(a[0]), "r"(a[1]), "r"(a[2]), "r"(a[3]), "r"(b[0]), "r"(b[1]));
}

__device__ __forceinline__ void cp16(uint32_t dst, const void* src, bool pred) {
    asm volatile("cp.async.cg.shared.global [%0], [%1], 16, %2;"
        :: "r"(dst), "l"(src), "r"(pred ? 16 : 0));
}
#define CP_COMMIT() asm volatile("cp.async.commit_group;" ::: "memory")
#define CP_WAIT1()  asm volatile("cp.async.wait_group 1;" ::: "memory")
#define CP_WAIT0()  asm volatile("cp.async.wait_group 0;" ::: "memory")

// smem: 3 stages, each = A(16384) + B(16384) = 32768. total 98304 -> 2 CTAs/SM.
// Rows 64B (32 halves), no padding; XOR swizzle: slot s stored at s ^ ((row>>1)&3).
#define PLN    8192
#define ABUF   16384
#define BUFSZ  32768
#define NSTAGE 3
#define SM_TOT 98304

// ============================================================
// Implicit-GEMM conv1d + BN + ReLU via mma.sync fp16 3-term split.
// BM=128 x BN=128, BK=32. 128 thr (4 warps, 2m x 2n), warp tile 64x64.
// 2 CTAs/SM, 3-stage pipeline. Loads interleaved with MMA phases.
// ============================================================
template<int KTAP, int S, int P, int CIN, bool SPLITOUT>
__global__ void __launch_bounds__(128, 2) conv_mma(
    const __half* __restrict__ Xh, const __half* __restrict__ Xl,
    const __half* __restrict__ Wh, const __half* __restrict__ Wl,
    const float* __restrict__ gam, const float* __restrict__ bet,
    const float* __restrict__ mu,  const float* __restrict__ var,
    __half* __restrict__ Yh, __half* __restrict__ Yl, float* __restrict__ Yf,
    int Tin, int Tout)
{
    extern __shared__ char smem[];
    const uint32_t sb = smem_u32(smem);
    const int tid = threadIdx.x;
    const int lane = tid & 31, w = tid >> 5;
    const int mw = w & 1, nw = w >> 1;
    const int b = blockIdx.z, m0 = blockIdx.y * 128, t0 = blockIdx.x * 128;
    constexpr int Kp = KTAP * CIN;
    constexpr int nchunk = Kp / 32;

    float acc[4][8][4];
    #pragma unroll
    for (int i = 0; i < 4; i++)
        #pragma unroll
        for (int j = 0; j < 8; j++)
            #pragma unroll
            for (int r = 0; r < 4; r++) acc[i][j][r] = 0.f;

    auto issue = [&](int kc, int st) {
        const int tap = (kc * 32) / CIN;
        const int ci0 = (kc * 32) % CIN;
        const uint32_t base = sb + st * BUFSZ;
        #pragma unroll
        for (int i = 0; i < 8; i++) {
            const int idx = i * 128 + tid;
            const int pl = idx >> 9;
            const int r = (idx >> 2) & 127, seg = idx & 3;
            const int sseg = seg ^ ((r >> 1) & 3);
            const __half* W = pl ? Wl : Wh;
            cp16(base + pl * PLN + r * 64 + sseg * 16,
                 W + (size_t)(m0 + r) * Kp + kc * 32 + seg * 8, true);
            const int t_in = (t0 + r) * S + tap - P;
            const bool ok = (t_in >= 0) && (t_in < Tin);
            const int tc = ok ? t_in : 0;
            const __half* X = pl ? Xl : Xh;
            cp16(base + ABUF + pl * PLN + r * 64 + sseg * 16,
                 X + ((size_t)b * Tin + tc) * CIN + ci0 + seg * 8, ok);
        }
    };

    const int r_a = mw * 64 + (lane & 15);
    const uint32_t aswz = (uint32_t)((r_a >> 1) & 3);
    const uint32_t abase = (uint32_t)(r_a * 64);
    const uint32_t as0 = (uint32_t)(lane >> 4);
    const int r_b = nw * 64 + (lane & 7) + ((lane >> 4) << 3);
    const uint32_t bswz = (uint32_t)((r_b >> 1) & 3);
    const uint32_t bbase = (uint32_t)(r_b * 64);
    const uint32_t bs0 = (uint32_t)((lane >> 3) & 1);

    issue(0, 0);
    CP_COMMIT();
    issue(1, 1);
    CP_COMMIT();

    for (int kc = 0; kc < nchunk; kc++) {
        if (kc + 1 < nchunk) CP_WAIT1(); else CP_WAIT0();
        __syncthreads();
        if (kc + 2 < nchunk) {
            issue(kc + 2, (kc + 2) % NSTAGE);
            CP_COMMIT();
        }
        const uint32_t sa  = sb + (kc % NSTAGE) * BUFSZ;
        const uint32_t sbB = sa + ABUF;
        #pragma unroll
        for (int ks = 0; ks < 2; ks++) {
            uint32_t af0[4][4], af1[4][4], bf0[8][2], bf1[8][2];
            const uint32_t bslot = ((bs0 + 2 * ks) ^ bswz) * 16;
            const uint32_t aslot = ((as0 + 2 * ks) ^ aswz) * 16;
            // ---- load hi planes ----
            #pragma unroll
            for (int nc = 0; nc < 4; nc++)
                LDMX4(bf0[2*nc][0], bf0[2*nc][1], bf0[2*nc+1][0], bf0[2*nc+1][1],
                      sbB + bbase + nc * 1024 + bslot);
            #pragma unroll
            for (int mt = 0; mt < 4; mt++)
                LDMX4(af0[mt][0], af0[mt][1], af0[mt][2], af0[mt][3],
                      sa + abase + mt * 1024 + aslot);
            // ---- phase 1: hi*hi (B-lo loads interleave under these MMAs) ----
            #pragma unroll
            for (int nc = 0; nc < 4; nc++)
                LDMX4(bf1[2*nc][0], bf1[2*nc][1], bf1[2*nc+1][0], bf1[2*nc+1][1],
                      sbB + PLN + bbase + nc * 1024 + bslot);
            #pragma unroll
            for (int mt = 0; mt < 4; mt++)
                #pragma unroll
                for (int nt = 0; nt < 8; nt++)
                    mma16816(acc[mt][nt], af0[mt], bf0[nt]);
            // ---- phase 2: hi*lo (A-lo loads interleave) ----
            #pragma unroll
            for (int mt = 0; mt < 4; mt++)
                LDMX4(af1[mt][0], af1[mt][1], af1[mt][2], af1[mt][3],
                      sa + PLN + abase + mt * 1024 + aslot);
            #pragma unroll
            for (int mt = 0; mt < 4; mt++)
                #pragma unroll
                for (int nt = 0; nt < 8; nt++)
                    mma16816(acc[mt][nt], af0[mt], bf1[nt]);
            // ---- phase 3: lo*hi ----
            #pragma unroll
            for (int mt = 0; mt < 4; mt++)
                #pragma unroll
                for (int nt = 0; nt < 8; nt++)
                    mma16816(acc[mt][nt], af1[mt], bf0[nt]);
        }
    }
    __syncthreads();

    // ---------- epilogue ----------
    float* eps = (float*)(smem + w * 18432);
    #pragma unroll
    for (int mt = 0; mt < 4; mt++)
        #pragma unroll
        for (int nt = 0; nt < 8; nt++)
            #pragma unroll
            for (int r = 0; r < 4; r++) {
                const int nl = nt * 8 + 2 * (lane & 3) + (r & 1);
                const int ml = mt * 16 + (lane >> 2) + ((r >> 1) << 3);
                eps[nl * 72 + ml] = acc[mt][nt][r];
            }
    __syncwarp();

    const int cg = m0 + mw * 64 + lane * 2;
    const float inv0 = gam[cg] * rsqrtf(var[cg] + 1e-5f);
    const float sh0  = bet[cg] - mu[cg] * inv0;
    const float inv1 = gam[cg + 1] * rsqrtf(var[cg + 1] + 1e-5f);
    const float sh1  = bet[cg + 1] - mu[cg + 1] * inv1;

    #pragma unroll 4
    for (int rn = 0; rn < 64; rn++) {
        const int t = t0 + nw * 64 + rn;
        if (t < Tout) {
            float v0 = fmaf(eps[rn * 72 + lane * 2], inv0, sh0);
            float v1 = fmaf(eps[rn * 72 + lane * 2 + 1], inv1, sh1);
            v0 = v0 > 0.f ? v0 : 0.f;
            v1 = v1 > 0.f ? v1 : 0.f;
            const size_t o = ((size_t)b * Tout + t) * CCH + cg;
            if (SPLITOUT) {
                const __half h0 = __float2half_rn(v0);
                const __half h1 = __float2half_rn(v1);
                const __half l0 = __float2half_rn(v0 - __half2float(h0));
                const __half l1 = __float2half_rn(v1 - __half2float(h1));
                *(__half2*)(Yh + o) = __halves2half2(h0, h1);
                *(__half2*)(Yl + o) = __halves2half2(l0, l1);
            } else {
                *(float2*)(Yf + o) = make_float2(v0, v1);
            }
        }
    }
}

// ============================================================
// Fused weight prep: [co][ci][k] -> [co][tap*Cpad+ci], hi/lo fp16.
// ============================================================
__device__ __forceinline__ void w_split(const float* __restrict__ src,
                                        __half* dh, __half* dl,
                                        int Cin, int Cpad, int K, int idx)
{
    const int ci = idx % Cpad;
    const int r  = idx / Cpad;
    const int k  = r % K, co = r / K;
    const float v = (ci < Cin) ? src[((size_t)co * Cin + ci) * K + k] : 0.f;
    const __half h = __float2half_rn(v);
    dh[idx] = h;
    dl[idx] = __float2half_rn(v - __half2float(h));
}

#define NW1 (768*3*128)
#define NW2 (768*3*768)
#define NW3 (768*4*768)
#define NWTOT (NW1 + 3*NW2 + NW3)

__global__ void prep_w_all(const float* __restrict__ w1, const float* __restrict__ w2,
                           const float* __restrict__ w3, const float* __restrict__ w4,
                           const float* __restrict__ w5)
{
    int idx = blockIdx.x * 256 + threadIdx.x;
    if (idx < NW1) { w_split(w1, g_W1h, g_W1l, 80, 128, 3, idx); return; }
    idx -= NW1;
    if (idx < NW2) { w_split(w2, g_W2h, g_W2l, 768, 768, 3, idx); return; }
    idx -= NW2;
    if (idx < NW3) { w_split(w3, g_W3h, g_W3l, 768, 768, 4, idx); return; }
    idx -= NW3;
    if (idx < NW2) { w_split(w4, g_W4h, g_W4l, 768, 768, 3, idx); return; }
    idx -= NW2;
    if (idx < NW2) { w_split(w5, g_W5h, g_W5l, 768, 768, 3, idx); return; }
}

// ============================================================
// Prep: transpose mels [b][80][1024] -> [b][1024][128] halves hi/lo (pad ch).
// ============================================================
__global__ void prep_mels(const float* __restrict__ mels)
{
    __shared__ float ts[80][33];
    const int b = blockIdx.y, t0 = blockIdx.x * 32, tid = threadIdx.x;
    const int tl = tid & 31, cw = tid >> 5;
    for (int c = cw; c < 80; c += 8)
        ts[c][tl] = mels[((size_t)b * 80 + c) * 1024 + t0 + tl];
    __syncthreads();
    const int c0 = (tid & 31) * 4, tw = tid >> 5;
    for (int tt = tw; tt < 32; tt += 8) {
        #pragma unroll
        for (int j = 0; j < 4; j++) {
            const int c = c0 + j;
            const float x = (c < 80) ? ts[c][tt] : 0.f;
            const __half h = __float2half_rn(x);
            const size_t o = ((size_t)b * 1024 + t0 + tt) * 128 + c;
            g_M1h[o] = h;
            g_M1l[o] = __float2half_rn(x - __half2float(h));
        }
    }
}

// ============================================================
// VQ prep: transpose embedding, ||e||^2, zero counts.
// ============================================================
__global__ void prep_vq(const float* __restrict__ E)
{
    const int e = blockIdx.x * 64 + threadIdx.x;
    float s = 0.f;
    #pragma unroll
    for (int d = 0; d < DDIM; d++) {
        const float v = E[(size_t)e * DDIM + d];
        s = fmaf(v, v, s);
        g_Et[d * MEMB + e] = v;
    }
    g_esq[e] = s;
    g_counts[e] = 0;
}

// ============================================================
// FUSED conv6 (1x1, 768->64) + bias + VQ (argmin, q_st, loss, counts).
// CTA: one batch b, 32 t. z tile lives in smem; no global z round-trip.
// ============================================================
__global__ __launch_bounds__(256) void conv6_vq_kernel(
    const float* __restrict__ X, const float* __restrict__ W6,
    const float* __restrict__ b6, const float* __restrict__ E,
    float* __restrict__ out)
{
    __shared__ float Xs[64][33];   // [ci][t]
    __shared__ float Ws[64][65];   // [d][ci]
    __shared__ float zs[32][65];   // [t][d]
    __shared__ float pw[8];
    const int tid = threadIdx.x;
    const int b   = blockIdx.y;
    const int t0  = blockIdx.x * 32;
    const int tdx = tid & 15;      // d group (4 d each)
    const int ttx = tid >> 4;      // t group (2 t each)

    float acc[4][2];
    #pragma unroll
    for (int i = 0; i < 4; i++) { acc[i][0] = 0.f; acc[i][1] = 0.f; }

    const int lc = tid & 63;
    const int lr = tid >> 6;

    for (int c0 = 0; c0 < CCH; c0 += 64) {
        #pragma unroll
        for (int r = 0; r < 8; r++) {
            const int t = lr + 4 * r;
            const int trow = t0 + t;
            Xs[lc][t] = (trow < TP)
                ? X[((size_t)b * TP + trow) * CCH + c0 + lc] : 0.f;
        }
        #pragma unroll
        for (int r = 0; r < 16; r++) {
            const int d = lr + r * 4;
            Ws[d][lc] = W6[(size_t)d * CCH + c0 + lc];
        }
        __syncthreads();
        #pragma unroll 8
        for (int ci = 0; ci < 64; ci++) {
            float wv[4], x[2];
            #pragma unroll
            for (int i = 0; i < 4; i++) wv[i] = Ws[tdx * 4 + i][ci];
            x[0] = Xs[ci][ttx * 2];
            x[1] = Xs[ci][ttx * 2 + 1];
            #pragma unroll
            for (int i = 0; i < 4; i++) {
                acc[i][0] = fmaf(wv[i], x[0], acc[i][0]);
                acc[i][1] = fmaf(wv[i], x[1], acc[i][1]);
            }
        }
        __syncthreads();
    }
    // stage z tile in smem
    #pragma unroll
    for (int i = 0; i < 4; i++) {
        const int d = tdx * 4 + i;
        const float bias = b6[d];
        zs[ttx * 2][d]     = acc[i][0] + bias;
        zs[ttx * 2 + 1][d] = acc[i][1] + bias;
    }
    __syncthreads();

    // ---- VQ: warp w handles local t = 4w .. 4w+3 ----
    const int w = tid >> 5, lane = tid & 31;
    float lsum = 0.f;
    #pragma unroll
    for (int j = 0; j < 4; j++) {
        const int tl = w * 4 + j;
        const int t  = t0 + tl;
        if (t < TP) {                          // warp-uniform condition
            float best = 3.4e38f;
            int   bidx = 0;
            #pragma unroll
            for (int i = 0; i < 16; i++) {
                const int e = lane + 32 * i;
                float dot = 0.f;
                #pragma unroll
                for (int d = 0; d < 64; d++)
                    dot = fmaf(zs[tl][d], g_Et[d * MEMB + e], dot);
                const float dist = g_esq[e] - 2.f * dot;
                if (dist < best) { best = dist; bidx = e; }
            }
            #pragma unroll
            for (int off = 16; off > 0; off >>= 1) {
                const float ob = __shfl_down_sync(0xFFFFFFFFu, best, off);
                const int   oi = __shfl_down_sync(0xFFFFFFFFu, bidx, off);
                if (ob < best || (ob == best && oi < bidx)) { best = ob; bidx = oi; }
            }
            bidx = __shfl_sync(0xFFFFFFFFu, bidx, 0);

            #pragma unroll
            for (int h = 0; h < 2; h++) {
                const int d   = lane + 32 * h;
                const float zv = zs[tl][d];
                const float q  = E[(size_t)bidx * 64 + d];
                out[((size_t)(b * TP + t)) * 64 + d] = zv + (q - zv);  // straight-through
                const float diff = zv - q;
                lsum = fmaf(diff, diff, lsum);
            }
            if (lane == 0) atomicAdd(&g_counts[bidx], 1);
        }
    }
    #pragma unroll
    for (int off = 16; off > 0; off >>= 1)
        lsum += __shfl_down_sync(0xFFFFFFFFu, lsum, off);
    if (lane == 0) pw[w] = lsum;
    __syncthreads();
    if (tid == 0) {
        float s = 0.f;
        #pragma unroll
        for (int i = 0; i < 8; i++) s += pw[i];
        g_partial[blockIdx.y * 16 + blockIdx.x] = s;
    }
}

// ============================================================
// Finalize: loss + perplexity.
// ============================================================
__global__ __launch_bounds__(1024) void finalize_kernel(float* __restrict__ out)
{
    __shared__ float sh[1024];
    const int tid = threadIdx.x;
    float s = 0.f;
    for (int i = tid; i < NPART; i += 1024) s += g_partial[i];
    sh[tid] = s; __syncthreads();
    for (int off = 512; off > 0; off >>= 1) {
        if (tid < off) sh[tid] += sh[tid + off];
        __syncthreads();
    }
    const float total = sh[0];
    __syncthreads();
    float h = 0.f;
    if (tid < MEMB) {
        const float p = (float)g_counts[tid] / (float)NVEC;
        h = p * logf(p + 1e-10f);
    }
    sh[tid] = h; __syncthreads();
    for (int off = 512; off > 0; off >>= 1) {
        if (tid < off) sh[tid] += sh[tid + off];
        __syncthreads();
    }
    if (tid == 0) {
        out[(size_t)NVEC * DDIM]     = 0.25f * total / (float)((size_t)NVEC * DDIM);
        out[(size_t)NVEC * DDIM + 1] = expf(-sh[0]);
    }
}

// ============================================================
// launch
// ============================================================
extern "C" void kernel_launch(void* const* d_in, const int* in_sizes, int n_in,
                              void* d_out, int out_size)
{
    const float* mels  = (const float*)d_in[0];
    const float* w1    = (const float*)d_in[1];
    const float* w2    = (const float*)d_in[2];
    const float* w3    = (const float*)d_in[3];
    const float* w4    = (const float*)d_in[4];
    const float* w5    = (const float*)d_in[5];
    const float* w6    = (const float*)d_in[6];
    const float* b6    = (const float*)d_in[7];
    const float* gamma = (const float*)d_in[8];
    const float* beta  = (const float*)d_in[9];
    const float* mean  = (const float*)d_in[10];
    const float* var   = (const float*)d_in[11];
    const float* emb   = (const float*)d_in[12];
    float* out = (float*)d_out;

    __half *XAh, *XAl, *XBh, *XBl, *M1h, *M1l;
    __half *W1h, *W1l, *W2h, *W2l, *W3h, *W3l, *W4h, *W4l, *W5h, *W5l;
    float *C5;
    cudaGetSymbolAddress((void**)&XAh, g_XAh);
    cudaGetSymbolAddress((void**)&XAl, g_XAl);
    cudaGetSymbolAddress((void**)&XBh, g_XBh);
    cudaGetSymbolAddress((void**)&XBl, g_XBl);
    cudaGetSymbolAddress((void**)&M1h, g_M1h);
    cudaGetSymbolAddress((void**)&M1l, g_M1l);
    cudaGetSymbolAddress((void**)&C5,  g_C5);
    cudaGetSymbolAddress((void**)&W1h, g_W1h); cudaGetSymbolAddress((void**)&W1l, g_W1l);
    cudaGetSymbolAddress((void**)&W2h, g_W2h); cudaGetSymbolAddress((void**)&W2l, g_W2l);
    cudaGetSymbolAddress((void**)&W3h, g_W3h); cudaGetSymbolAddress((void**)&W3l, g_W3l);
    cudaGetSymbolAddress((void**)&W4h, g_W4h); cudaGetSymbolAddress((void**)&W4l, g_W4l);
    cudaGetSymbolAddress((void**)&W5h, g_W5h); cudaGetSymbolAddress((void**)&W5l, g_W5l);

    cudaFuncSetAttribute(conv_mma<3,1,0,128,true>,  cudaFuncAttributeMaxDynamicSharedMemorySize, SM_TOT);
    cudaFuncSetAttribute(conv_mma<3,1,1,768,true>,  cudaFuncAttributeMaxDynamicSharedMemorySize, SM_TOT);
    cudaFuncSetAttribute(conv_mma<4,2,1,768,true>,  cudaFuncAttributeMaxDynamicSharedMemorySize, SM_TOT);
    cudaFuncSetAttribute(conv_mma<3,1,1,768,false>, cudaFuncAttributeMaxDynamicSharedMemorySize, SM_TOT);

    // --- prep ---
    prep_w_all<<<(NWTOT + 255)/256, 256>>>(w1, w2, w3, w4, w5);
    prep_mels<<<dim3(32, BATCH), 256>>>(mels);

    // --- conv stack (fp16 3-term split, 64x64 warp tile, 2 CTAs/SM) ---
    conv_mma<3,1,0,128,true><<<dim3(8, 6, BATCH), 128, SM_TOT>>>(
        M1h, M1l, W1h, W1l, gamma, beta, mean, var,
        XAh, XAl, nullptr, 1024, 1022);
    conv_mma<3,1,1,768,true><<<dim3(8, 6, BATCH), 128, SM_TOT>>>(
        XAh, XAl, W2h, W2l, gamma+CCH, beta+CCH, mean+CCH, var+CCH,
        XBh, XBl, nullptr, 1022, 1022);
    conv_mma<4,2,1,768,true><<<dim3(4, 6, BATCH), 128, SM_TOT>>>(
        XBh, XBl, W3h, W3l, gamma+2*CCH, beta+2*CCH, mean+2*CCH, var+2*CCH,
        XAh, XAl, nullptr, 1022, 511);
    conv_mma<3,1,1,768,true><<<dim3(4, 6, BATCH), 128, SM_TOT>>>(
        XAh, XAl, W4h, W4l, gamma+3*CCH, beta+3*CCH, mean+3*CCH, var+3*CCH,
        XBh, XBl, nullptr, 511, 511);
    conv_mma<3,1,1,768,false><<<dim3(4, 6, BATCH), 128, SM_TOT>>>(
        XBh, XBl, W5h, W5l, gamma+4*CCH, beta+4*CCH, mean+4*CCH, var+4*CCH,
        nullptr, nullptr, C5, 511, 511);

    // --- fused tail ---
    prep_vq<<<8, 64>>>(emb);
    conv6_vq_kernel<<<dim3(16, BATCH), 256>>>(C5, w6, b6, emb, out);
    finalize_kernel<<<1, 1024>>>(out);
}

// round 11
// speedup vs baseline: 1.9391x; 1.0583x over previous
#include <cuda_runtime.h>
#include <cuda_fp16.h>
#include <math.h>
#include <stdint.h>

// ---------------- problem constants ----------------
#define BATCH 32
#define CCH   768
#define DDIM  64
#define MEMB  512
#define TP    511
#define NVEC  (BATCH * TP)
#define NPART 512              // conv6_vq grid: 16 x 32

// ---------------- device scratch (static) ----------------
__device__ __half g_XAh[(size_t)BATCH * 1022 * CCH];
__device__ __half g_XAl[(size_t)BATCH * 1022 * CCH];
__device__ __half g_XBh[(size_t)BATCH * 1022 * CCH];
__device__ __half g_XBl[(size_t)BATCH * 1022 * CCH];
__device__ __half g_M1h[(size_t)BATCH * 1024 * 96];
__device__ __half g_M1l[(size_t)BATCH * 1024 * 96];
__device__ __half g_W1h[768 * 3 * 96], g_W1l[768 * 3 * 96];
__device__ __half g_W2h[768 * 3 * 768], g_W2l[768 * 3 * 768];
__device__ __half g_W3h[768 * 4 * 768], g_W3l[768 * 4 * 768];
__device__ __half g_W4h[768 * 3 * 768], g_W4l[768 * 3 * 768];
__device__ __half g_W5h[768 * 3 * 768], g_W5l[768 * 3 * 768];
__device__ float g_C5[(size_t)BATCH * TP * CCH];     // [b][t][c] fp32
__device__ float g_Et[DDIM * MEMB];
__device__ float g_esq[MEMB];
__device__ int   g_counts[MEMB];
__device__ float g_partial[NPART];

// ---------------- helpers ----------------
__device__ __forceinline__ uint32_t smem_u32(const void* p) {
    uint32_t a;
    asm("{ .reg .u64 t; cvta.to.shared.u64 t, %1; cvt.u32.u64 %0, t; }"
        : "=r"(a) : "l"(p));
    return a;
}

#define LDMX4(r0, r1, r2, r3, addr) \
    asm volatile("ldmatrix.sync.aligned.m8n8.x4.shared.b16 {%0,%1,%2,%3}, [%4];" \
        : "=r"(r0), "=r"(r1), "=r"(r2), "=r"(r3) : "r"(addr))

__device__ __forceinline__ void mma16816(float* d, const uint32_t* a, const uint32_t* b) {
    asm volatile(
        "mma.sync.aligned.m16n8k16.row.col.f32.f16.f16.f32 "
        "{%0,%1,%2,%3}, {%4,%5,%6,%7}, {%8,%9}, {%0,%1,%2,%3};"
        : "+f"(d[0]), "+f"(d[1]), "+f"(d[2]), "+f"(d[3])
        : "r"(a[0]), "r"(a[1]), "r"(a[2]), "r"(a[3]), "r"(b[0]), "r"(b[1]));
}

__device__ __forceinline__ void cp16(uint32_t dst, const void* src, bool pred) {
    asm volatile("cp.async.cg.shared.global [%0], [%1], 16, %2;"
        :: "r"(dst), "l"(src), "r"(pred ? 16 : 0));
}
#define CP_COMMIT() asm volatile("cp.async.commit_group;" ::: "memory")
#define CP_WAIT1()  asm volatile("cp.async.wait_group 1;" ::: "memory")
#define CP_WAIT0()  asm volatile("cp.async.wait_group 0;" ::: "memory")

// smem: 3 stages, each = A(16384) + B(16384) = 32768. total 98304 -> 2 CTAs/SM.
// Rows 64B (32 halves), no padding; XOR swizzle: slot s stored at s ^ ((row>>1)&3).
#define PLN    8192
#define ABUF   16384
#define BUFSZ  32768
#define NSTAGE 3
#define SM_TOT 98304

// ============================================================
// Implicit-GEMM conv1d + BN + ReLU via mma.sync fp16 3-term split.
// BM=128 x BN=128, BK=32. 128 thr (4 warps, 2m x 2n), warp tile 64x64.
// 2 CTAs/SM, 3-stage pipeline (R9 loop structure; cp.async issued
// after the frag-load block so LDSM critical path starts first).
// ============================================================
template<int KTAP, int S, int P, int CIN, bool SPLITOUT>
__global__ void __launch_bounds__(128, 2) conv_mma(
    const __half* __restrict__ Xh, const __half* __restrict__ Xl,
    const __half* __restrict__ Wh, const __half* __restrict__ Wl,
    const float* __restrict__ gam, const float* __restrict__ bet,
    const float* __restrict__ mu,  const float* __restrict__ var,
    __half* __restrict__ Yh, __half* __restrict__ Yl, float* __restrict__ Yf,
    int Tin, int Tout)
{
    extern __shared__ char smem[];
    const uint32_t sb = smem_u32(smem);
    const int tid = threadIdx.x;
    const int lane = tid & 31, w = tid >> 5;
    const int mw = w & 1, nw = w >> 1;         // warp grid: 2(m) x 2(n)
    const int b = blockIdx.z, m0 = blockIdx.y * 128, t0 = blockIdx.x * 128;
    constexpr int Kp = KTAP * CIN;
    constexpr int nchunk = Kp / 32;

    float acc[4][8][4];
    #pragma unroll
    for (int i = 0; i < 4; i++)
        #pragma unroll
        for (int j = 0; j < 8; j++)
            #pragma unroll
            for (int r = 0; r < 4; r++) acc[i][j][r] = 0.f;

    auto issue = [&](int kc, int st) {
        const int tap = (kc * 32) / CIN;
        const int ci0 = (kc * 32) % CIN;
        const uint32_t base = sb + st * BUFSZ;
        #pragma unroll
        for (int i = 0; i < 8; i++) {
            const int idx = i * 128 + tid;
            const int pl = idx >> 9;
            const int r = (idx >> 2) & 127, seg = idx & 3;
            const int sseg = seg ^ ((r >> 1) & 3);
            const __half* W = pl ? Wl : Wh;
            cp16(base + pl * PLN + r * 64 + sseg * 16,
                 W + (size_t)(m0 + r) * Kp + kc * 32 + seg * 8, true);
            const int t_in = (t0 + r) * S + tap - P;
            const bool ok = (t_in >= 0) && (t_in < Tin);
            const int tc = ok ? t_in : 0;
            const __half* X = pl ? Xl : Xh;
            cp16(base + ABUF + pl * PLN + r * 64 + sseg * 16,
                 X + ((size_t)b * Tin + tc) * CIN + ci0 + seg * 8, ok);
        }
    };

    const int r_a = mw * 64 + (lane & 15);
    const uint32_t aswz = (uint32_t)((r_a >> 1) & 3);
    const uint32_t abase = (uint32_t)(r_a * 64);
    const uint32_t as0 = (uint32_t)(lane >> 4);
    const int r_b = nw * 64 + (lane & 7) + ((lane >> 4) << 3);
    const uint32_t bswz = (uint32_t)((r_b >> 1) & 3);
    const uint32_t bbase = (uint32_t)(r_b * 64);
    const uint32_t bs0 = (uint32_t)((lane >> 3) & 1);

    issue(0, 0);
    CP_COMMIT();
    issue(1, 1);
    CP_COMMIT();

    for (int kc = 0; kc < nchunk; kc++) {
        if (kc + 1 < nchunk) CP_WAIT1(); else CP_WAIT0();
        __syncthreads();        // stage kc visible; stage (kc-1) free for reuse
        const uint32_t sa  = sb + (kc % NSTAGE) * BUFSZ;
        const uint32_t sbB = sa + ABUF;
        #pragma unroll
        for (int ks = 0; ks < 2; ks++) {
            uint32_t af[2][4][4], bf[2][8][2];
            const uint32_t bslot = ((bs0 + 2 * ks) ^ bswz) * 16;
            #pragma unroll
            for (int nc = 0; nc < 4; nc++) {
                LDMX4(bf[0][2*nc][0], bf[0][2*nc][1], bf[0][2*nc+1][0], bf[0][2*nc+1][1],
                      sbB + bbase + nc * 1024 + bslot);
                LDMX4(bf[1][2*nc][0], bf[1][2*nc][1], bf[1][2*nc+1][0], bf[1][2*nc+1][1],
                      sbB + PLN + bbase + nc * 1024 + bslot);
            }
            const uint32_t aslot = ((as0 + 2 * ks) ^ aswz) * 16;
            #pragma unroll
            for (int mt = 0; mt < 4; mt++)
                LDMX4(af[0][mt][0], af[0][mt][1], af[0][mt][2], af[0][mt][3],
                      sa + abase + mt * 1024 + aslot);
            #pragma unroll
            for (int mt = 0; mt < 4; mt++)
                LDMX4(af[1][mt][0], af[1][mt][1], af[1][mt][2], af[1][mt][3],
                      sa + PLN + abase + mt * 1024 + aslot);
            // cp.async burst for stage kc+2, issued AFTER frag loads so the
            // LDSM critical path starts first; drains under the MMA phases.
            if (ks == 0 && kc + 2 < nchunk) {
                issue(kc + 2, (kc + 2) % NSTAGE);
                CP_COMMIT();
            }
            // 3-phase ordering: 32 independent accumulator chains per phase
            #pragma unroll
            for (int mt = 0; mt < 4; mt++)
                #pragma unroll
                for (int nt = 0; nt < 8; nt++)
                    mma16816(acc[mt][nt], af[0][mt], bf[0][nt]);   // hi*hi
            #pragma unroll
            for (int mt = 0; mt < 4; mt++)
                #pragma unroll
                for (int nt = 0; nt < 8; nt++)
                    mma16816(acc[mt][nt], af[0][mt], bf[1][nt]);   // hi*lo
            #pragma unroll
            for (int mt = 0; mt < 4; mt++)
                #pragma unroll
                for (int nt = 0; nt < 8; nt++)
                    mma16816(acc[mt][nt], af[1][mt], bf[0][nt]);   // lo*hi
        }
    }
    __syncthreads();

    // ---------- epilogue ----------
    float* eps = (float*)(smem + w * 18432);
    #pragma unroll
    for (int mt = 0; mt < 4; mt++)
        #pragma unroll
        for (int nt = 0; nt < 8; nt++)
            #pragma unroll
            for (int r = 0; r < 4; r++) {
                const int nl = nt * 8 + 2 * (lane & 3) + (r & 1);
                const int ml = mt * 16 + (lane >> 2) + ((r >> 1) << 3);
                eps[nl * 72 + ml] = acc[mt][nt][r];
            }
    __syncwarp();

    const int cg = m0 + mw * 64 + lane * 2;
    const float inv0 = gam[cg] * rsqrtf(var[cg] + 1e-5f);
    const float sh0  = bet[cg] - mu[cg] * inv0;
    const float inv1 = gam[cg + 1] * rsqrtf(var[cg + 1] + 1e-5f);
    const float sh1  = bet[cg + 1] - mu[cg + 1] * inv1;

    #pragma unroll 4
    for (int rn = 0; rn < 64; rn++) {
        const int t = t0 + nw * 64 + rn;
        if (t < Tout) {
            float v0 = fmaf(eps[rn * 72 + lane * 2], inv0, sh0);
            float v1 = fmaf(eps[rn * 72 + lane * 2 + 1], inv1, sh1);
            v0 = v0 > 0.f ? v0 : 0.f;
            v1 = v1 > 0.f ? v1 : 0.f;
            const size_t o = ((size_t)b * Tout + t) * CCH + cg;
            if (SPLITOUT) {
                const __half h0 = __float2half_rn(v0);
                const __half h1 = __float2half_rn(v1);
                const __half l0 = __float2half_rn(v0 - __half2float(h0));
                const __half l1 = __float2half_rn(v1 - __half2float(h1));
                *(__half2*)(Yh + o) = __halves2half2(h0, h1);
                *(__half2*)(Yl + o) = __halves2half2(l0, l1);
            } else {
                *(float2*)(Yf + o) = make_float2(v0, v1);
            }
        }
    }
}

// ============================================================
// Fused weight prep: [co][ci][k] -> [co][tap*Cpad+ci], hi/lo fp16.
// ============================================================
__device__ __forceinline__ void w_split(const float* __restrict__ src,
                                        __half* dh, __half* dl,
                                        int Cin, int Cpad, int K, int idx)
{
    const int ci = idx % Cpad;
    const int r  = idx / Cpad;
    const int k  = r % K, co = r / K;
    const float v = (ci < Cin) ? src[((size_t)co * Cin + ci) * K + k] : 0.f;
    const __half h = __float2half_rn(v);
    dh[idx] = h;
    dl[idx] = __float2half_rn(v - __half2float(h));
}

#define NW1 (768*3*96)
#define NW2 (768*3*768)
#define NW3 (768*4*768)
#define NWTOT (NW1 + 3*NW2 + NW3)

__global__ void prep_w_all(const float* __restrict__ w1, const float* __restrict__ w2,
                           const float* __restrict__ w3, const float* __restrict__ w4,
                           const float* __restrict__ w5)
{
    int idx = blockIdx.x * 256 + threadIdx.x;
    if (idx < NW1) { w_split(w1, g_W1h, g_W1l, 80, 96, 3, idx); return; }
    idx -= NW1;
    if (idx < NW2) { w_split(w2, g_W2h, g_W2l, 768, 768, 3, idx); return; }
    idx -= NW2;
    if (idx < NW3) { w_split(w3, g_W3h, g_W3l, 768, 768, 4, idx); return; }
    idx -= NW3;
    if (idx < NW2) { w_split(w4, g_W4h, g_W4l, 768, 768, 3, idx); return; }
    idx -= NW2;
    if (idx < NW2) { w_split(w5, g_W5h, g_W5l, 768, 768, 3, idx); return; }
}

// ============================================================
// Prep: transpose mels [b][80][1024] -> [b][1024][96] halves hi/lo (pad ch).
// ============================================================
__global__ void prep_mels(const float* __restrict__ mels)
{
    __shared__ float ts[80][33];
    const int b = blockIdx.y, t0 = blockIdx.x * 32, tid = threadIdx.x;
    const int tl = tid & 31, cw = tid >> 5;
    for (int c = cw; c < 80; c += 8)
        ts[c][tl] = mels[((size_t)b * 80 + c) * 1024 + t0 + tl];
    __syncthreads();
    const int c0 = (tid & 31) * 4, tw = tid >> 5;
    for (int tt = tw; tt < 32; tt += 8) {
        #pragma unroll
        for (int j = 0; j < 4; j++) {
            const int c = c0 + j;
            if (c < 96) {
                const float x = (c < 80) ? ts[c][tt] : 0.f;
                const __half h = __float2half_rn(x);
                const size_t o = ((size_t)b * 1024 + t0 + tt) * 96 + c;
                g_M1h[o] = h;
                g_M1l[o] = __float2half_rn(x - __half2float(h));
            }
        }
    }
}

// ============================================================
// VQ prep: transpose embedding, ||e||^2, zero counts.
// ============================================================
__global__ void prep_vq(const float* __restrict__ E)
{
    const int e = blockIdx.x * 64 + threadIdx.x;
    float s = 0.f;
    #pragma unroll
    for (int d = 0; d < DDIM; d++) {
        const float v = E[(size_t)e * DDIM + d];
        s = fmaf(v, v, s);
        g_Et[d * MEMB + e] = v;
    }
    g_esq[e] = s;
    g_counts[e] = 0;
}

// ============================================================
// FUSED conv6 (1x1, 768->64) + bias + VQ (argmin, q_st, loss, counts).
// CTA: one batch b, 32 t. z tile lives in smem; no global z round-trip.
// ============================================================
__global__ __launch_bounds__(256) void conv6_vq_kernel(
    const float* __restrict__ X, const float* __restrict__ W6,
    const float* __restrict__ b6, const float* __restrict__ E,
    float* __restrict__ out)
{
    __shared__ float Xs[64][33];   // [ci][t]
    __shared__ float Ws[64][65];   // [d][ci]
    __shared__ float zs[32][65];   // [t][d]
    __shared__ float pw[8];
    const int tid = threadIdx.x;
    const int b   = blockIdx.y;
    const int t0  = blockIdx.x * 32;
    const int tdx = tid & 15;
    const int ttx = tid >> 4;

    float acc[4][2];
    #pragma unroll
    for (int i = 0; i < 4; i++) { acc[i][0] = 0.f; acc[i][1] = 0.f; }

    const int lc = tid & 63;
    const int lr = tid >> 6;

    for (int c0 = 0; c0 < CCH; c0 += 64) {
        #pragma unroll
        for (int r = 0; r < 8; r++) {
            const int t = lr + 4 * r;
            const int trow = t0 + t;
            Xs[lc][t] = (trow < TP)
                ? X[((size_t)b * TP + trow) * CCH + c0 + lc] : 0.f;
        }
        #pragma unroll
        for (int r = 0; r < 16; r++) {
            const int d = lr + r * 4;
            Ws[d][lc] = W6[(size_t)d * CCH + c0 + lc];
        }
        __syncthreads();
        #pragma unroll 8
        for (int ci = 0; ci < 64; ci++) {
            float wv[4], x[2];
            #pragma unroll
            for (int i = 0; i < 4; i++) wv[i] = Ws[tdx * 4 + i][ci];
            x[0] = Xs[ci][ttx * 2];
            x[1] = Xs[ci][ttx * 2 + 1];
            #pragma unroll
            for (int i = 0; i < 4; i++) {
                acc[i][0] = fmaf(wv[i], x[0], acc[i][0]);
                acc[i][1] = fmaf(wv[i], x[1], acc[i][1]);
            }
        }
        __syncthreads();
    }
    #pragma unroll
    for (int i = 0; i < 4; i++) {
        const int d = tdx * 4 + i;
        const float bias = b6[d];
        zs[ttx * 2][d]     = acc[i][0] + bias;
        zs[ttx * 2 + 1][d] = acc[i][1] + bias;
    }
    __syncthreads();

    // ---- VQ: warp w handles local t = 4w .. 4w+3 ----
    const int w = tid >> 5, lane = tid & 31;
    float lsum = 0.f;
    #pragma unroll
    for (int j = 0; j < 4; j++) {
        const int tl = w * 4 + j;
        const int t  = t0 + tl;
        if (t < TP) {
            float best = 3.4e38f;
            int   bidx = 0;
            #pragma unroll
            for (int i = 0; i < 16; i++) {
                const int e = lane + 32 * i;
                float dot = 0.f;
                #pragma unroll
                for (int d = 0; d < 64; d++)
                    dot = fmaf(zs[tl][d], g_Et[d * MEMB + e], dot);
                const float dist = g_esq[e] - 2.f * dot;
                if (dist < best) { best = dist; bidx = e; }
            }
            #pragma unroll
            for (int off = 16; off > 0; off >>= 1) {
                const float ob = __shfl_down_sync(0xFFFFFFFFu, best, off);
                const int   oi = __shfl_down_sync(0xFFFFFFFFu, bidx, off);
                if (ob < best || (ob == best && oi < bidx)) { best = ob; bidx = oi; }
            }
            bidx = __shfl_sync(0xFFFFFFFFu, bidx, 0);

            #pragma unroll
            for (int h = 0; h < 2; h++) {
                const int d   = lane + 32 * h;
                const float zv = zs[tl][d];
                const float q  = E[(size_t)bidx * 64 + d];
                out[((size_t)(b * TP + t)) * 64 + d] = zv + (q - zv);
                const float diff = zv - q;
                lsum = fmaf(diff, diff, lsum);
            }
            if (lane == 0) atomicAdd(&g_counts[bidx], 1);
        }
    }
    #pragma unroll
    for (int off = 16; off > 0; off >>= 1)
        lsum += __shfl_down_sync(0xFFFFFFFFu, lsum, off);
    if (lane == 0) pw[w] = lsum;
    __syncthreads();
    if (tid == 0) {
        float s = 0.f;
        #pragma unroll
        for (int i = 0; i < 8; i++) s += pw[i];
        g_partial[blockIdx.y * 16 + blockIdx.x] = s;
    }
}

// ============================================================
// Finalize: loss + perplexity.
// ============================================================
__global__ __launch_bounds__(1024) void finalize_kernel(float* __restrict__ out)
{
    __shared__ float sh[1024];
    const int tid = threadIdx.x;
    float s = 0.f;
    for (int i = tid; i < NPART; i += 1024) s += g_partial[i];
    sh[tid] = s; __syncthreads();
    for (int off = 512; off > 0; off >>= 1) {
        if (tid < off) sh[tid] += sh[tid + off];
        __syncthreads();
    }
    const float total = sh[0];
    __syncthreads();
    float h = 0.f;
    if (tid < MEMB) {
        const float p = (float)g_counts[tid] / (float)NVEC;
        h = p * logf(p + 1e-10f);
    }
    sh[tid] = h; __syncthreads();
    for (int off = 512; off > 0; off >>= 1) {
        if (tid < off) sh[tid] += sh[tid + off];
        __syncthreads();
    }
    if (tid == 0) {
        out[(size_t)NVEC * DDIM]     = 0.25f * total / (float)((size_t)NVEC * DDIM);
        out[(size_t)NVEC * DDIM + 1] = expf(-sh[0]);
    }
}

// ============================================================
// launch
// ============================================================
extern "C" void kernel_launch(void* const* d_in, const int* in_sizes, int n_in,
                              void* d_out, int out_size)
{
    const float* mels  = (const float*)d_in[0];
    const float* w1    = (const float*)d_in[1];
    const float* w2    = (const float*)d_in[2];
    const float* w3    = (const float*)d_in[3];
    const float* w4    = (const float*)d_in[4];
    const float* w5    = (const float*)d_in[5];
    const float* w6    = (const float*)d_in[6];
    const float* b6    = (const float*)d_in[7];
    const float* gamma = (const float*)d_in[8];
    const float* beta  = (const float*)d_in[9];
    const float* mean  = (const float*)d_in[10];
    const float* var   = (const float*)d_in[11];
    const float* emb   = (const float*)d_in[12];
    float* out = (float*)d_out;

    __half *XAh, *XAl, *XBh, *XBl, *M1h, *M1l;
    __half *W1h, *W1l, *W2h, *W2l, *W3h, *W3l, *W4h, *W4l, *W5h, *W5l;
    float *C5;
    cudaGetSymbolAddress((void**)&XAh, g_XAh);
    cudaGetSymbolAddress((void**)&XAl, g_XAl);
    cudaGetSymbolAddress((void**)&XBh, g_XBh);
    cudaGetSymbolAddress((void**)&XBl, g_XBl);
    cudaGetSymbolAddress((void**)&M1h, g_M1h);
    cudaGetSymbolAddress((void**)&M1l, g_M1l);
    cudaGetSymbolAddress((void**)&C5,  g_C5);
    cudaGetSymbolAddress((void**)&W1h, g_W1h); cudaGetSymbolAddress((void**)&W1l, g_W1l);
    cudaGetSymbolAddress((void**)&W2h, g_W2h); cudaGetSymbolAddress((void**)&W2l, g_W2l);
    cudaGetSymbolAddress((void**)&W3h, g_W3h); cudaGetSymbolAddress((void**)&W3l, g_W3l);
    cudaGetSymbolAddress((void**)&W4h, g_W4h); cudaGetSymbolAddress((void**)&W4l, g_W4l);
    cudaGetSymbolAddress((void**)&W5h, g_W5h); cudaGetSymbolAddress((void**)&W5l, g_W5l);

    cudaFuncSetAttribute(conv_mma<3,1,0,96,true>,   cudaFuncAttributeMaxDynamicSharedMemorySize, SM_TOT);
    cudaFuncSetAttribute(conv_mma<3,1,1,768,true>,  cudaFuncAttributeMaxDynamicSharedMemorySize, SM_TOT);
    cudaFuncSetAttribute(conv_mma<4,2,1,768,true>,  cudaFuncAttributeMaxDynamicSharedMemorySize, SM_TOT);
    cudaFuncSetAttribute(conv_mma<3,1,1,768,false>, cudaFuncAttributeMaxDynamicSharedMemorySize, SM_TOT);

    // --- prep ---
    prep_w_all<<<(NWTOT + 255)/256, 256>>>(w1, w2, w3, w4, w5);
    prep_mels<<<dim3(32, BATCH), 256>>>(mels);

    // --- conv stack (fp16 3-term split, 64x64 warp tile, 2 CTAs/SM) ---
    conv_mma<3,1,0,96,true><<<dim3(8, 6, BATCH), 128, SM_TOT>>>(
        M1h, M1l, W1h, W1l, gamma, beta, mean, var,
        XAh, XAl, nullptr, 1024, 1022);
    conv_mma<3,1,1,768,true><<<dim3(8, 6, BATCH), 128, SM_TOT>>>(
        XAh, XAl, W2h, W2l, gamma+CCH, beta+CCH, mean+CCH, var+CCH,
        XBh, XBl, nullptr, 1022, 1022);
    conv_mma<4,2,1,768,true><<<dim3(4, 6, BATCH), 128, SM_TOT>>>(
        XBh, XBl, W3h, W3l, gamma+2*CCH, beta+2*CCH, mean+2*CCH, var+2*CCH,
        XAh, XAl, nullptr, 1022, 511);
    conv_mma<3,1,1,768,true><<<dim3(4, 6, BATCH), 128, SM_TOT>>>(
        XAh, XAl, W4h, W4l, gamma+3*CCH, beta+3*CCH, mean+3*CCH, var+3*CCH,
        XBh, XBl, nullptr, 511, 511);
    conv_mma<3,1,1,768,false><<<dim3(4, 6, BATCH), 128, SM_TOT>>>(
        XBh, XBl, W5h, W5l, gamma+4*CCH, beta+4*CCH, mean+4*CCH, var+4*CCH,
        nullptr, nullptr, C5, 511, 511);

    // --- fused tail ---
    prep_vq<<<8, 64>>>(emb);
    conv6_vq_kernel<<<dim3(16, BATCH), 256>>>(C5, w6, b6, emb, out);
    finalize_kernel<<<1, 1024>>>(out);
}